// round 3
// baseline (speedup 1.0000x reference)
#include <cuda_runtime.h>
#include <math.h>
#include <stdint.h>

#define BB 4
#define NN 25600
#define DD 64
#define RR (3*NN)
#define SPLITX 80            // blocks per batch; 320 nodes per block (2 grid rows)
#define NODES_PER_BLK (NN/SPLITX)
#define TILE 16              // nodes per iteration
#define ROWS (3*TILE)        // 48 k-rows per iteration
#define NPART (SPLITX*2)     // 2 k-groups per block

typedef unsigned long long ull;

__device__ float g_part[(size_t)BB*NPART*DD*DD];
__device__ float g_M[BB*DD*DD];
__device__ float g_trace[BB];
__device__ int   g_rowptr[NN+1];

#define PK2(dst, lo, hi) asm("mov.b64 %0, {%1,%2};" : "=l"(dst) : "f"(lo), "f"(hi))
#define FMA2(acc, a, b) asm("fma.rn.f32x2 %0, %1, %2, %0;" : "+l"(acc) : "l"(a), "l"(b))

// Build CSR row pointers from the lexicographically sorted e0 array.
__global__ void k_rowptr(const int* __restrict__ e0, int E){
  int i = blockIdx.x*blockDim.x + threadIdx.x;
  if(i >= E) return;
  int cur  = e0[i];
  int prev = (i==0) ? -1 : e0[i-1];
  for(int n = prev+1; n <= cur; n++) g_rowptr[n] = i;
  if(i == E-1){
    for(int n = cur+1; n <= NN; n++) g_rowptr[n] = E;
  }
}

// Fused: per 16-node tile, compute P = LJ rows, Z = Lc^{-1} BTJ rows into
// shared, then accumulate M_partial = J^T P - Z^T Z with packed f32x2 FMA.
__global__ void __launch_bounds__(256, 2) k_fused(const float* __restrict__ x,
                                                  const float* __restrict__ J,
                                                  const int* __restrict__ e1)
{
  __shared__ float sJ [ROWS*64];
  __shared__ float sP [ROWS*64];
  __shared__ float sZ [ROWS*64];
  __shared__ float sZn[ROWS*64];

  int b    = blockIdx.y;
  int tid  = threadIdx.x;
  int warp = tid >> 5;
  int lane = tid & 31;

  const float* xb = x + (size_t)b*NN*3;
  const float* Jb = J + (size_t)b*RR*DD;

  // gram thread mapping: 2 k-groups of 128 threads
  int g  = tid >> 7;          // 0..1
  int t  = tid & 127;
  int ty = t >> 3;            // 0..15 -> 4 output rows each
  int tx = t & 7;             // 0..7  -> 8 output cols each

  ull acc[4][4];
  #pragma unroll
  for(int i=0;i<4;i++)
    #pragma unroll
    for(int j=0;j<4;j++) acc[i][j] = 0ull;

  int nodeBase = blockIdx.x * NODES_PER_BLK;
  const int iters = NODES_PER_BLK / TILE;   // 20

  for(int it = 0; it < iters; it++){
    // ---- phase A: 8 warps x 2 nodes -> P, Z, -Z, J rows into shared ----
    __syncthreads();
    #pragma unroll
    for(int sub = 0; sub < 2; sub++){
      int si = warp*2 + sub;                 // node slot 0..15
      int n  = nodeBase + it*TILE + si;

      int rs = g_rowptr[n], re = g_rowptr[n+1];
      float deg = (float)(re - rs);
      float xn0 = xb[3*n], xn1 = xb[3*n+1], xn2 = xb[3*n+2];

      float g10x=0,g10y=0,g11x=0,g11y=0,g12x=0,g12y=0;
      float g20x=0,g20y=0,g21x=0,g21y=0,g22x=0,g22y=0;
      float c00=0,c11=0,c22=0,c01=0,c02=0,c12=0;
      float vs0=0,vs1=0,vs2=0;

      for(int e = rs; e < re; e++){
        int m = e1[e];
        float v0 = xn0 - xb[3*m];
        float v1 = xn1 - xb[3*m+1];
        float v2 = xn2 - xb[3*m+2];
        const float2* Jm = reinterpret_cast<const float2*>(Jb + (size_t)m*192);
        float2 j0 = Jm[lane];
        float2 j1 = Jm[32+lane];
        float2 j2 = Jm[64+lane];
        g10x += j0.x; g10y += j0.y;
        g11x += j1.x; g11y += j1.y;
        g12x += j2.x; g12y += j2.y;
        g20x += v1*j2.x - v2*j1.x;  g20y += v1*j2.y - v2*j1.y;
        g21x += v2*j0.x - v0*j2.x;  g21y += v2*j0.y - v0*j2.y;
        g22x += v0*j1.x - v1*j0.x;  g22y += v0*j1.y - v1*j0.y;
        float vv = v0*v0 + v1*v1 + v2*v2;
        c00 += vv - v0*v0;
        c11 += vv - v1*v1;
        c22 += vv - v2*v2;
        c01 -= v0*v1; c02 -= v0*v2; c12 -= v1*v2;
        vs0 += v0; vs1 += v1; vs2 += v2;
      }

      const float2* Jn = reinterpret_cast<const float2*>(Jb + (size_t)n*192);
      float2 a0 = Jn[lane], a1 = Jn[32+lane], a2 = Jn[64+lane];

      // J rows to shared
      float2* sj = reinterpret_cast<float2*>(sJ + (3*si)*64);
      sj[lane] = a0; sj[32+lane] = a1; sj[64+lane] = a2;

      // P = 2*(deg*J3n - sum_m J3[m])
      float2 p0, p1, p2;
      p0.x = 2.f*(deg*a0.x - g10x); p0.y = 2.f*(deg*a0.y - g10y);
      p1.x = 2.f*(deg*a1.x - g11x); p1.y = 2.f*(deg*a1.y - g11y);
      p2.x = 2.f*(deg*a2.x - g12x); p2.y = 2.f*(deg*a2.y - g12y);
      float2* sp = reinterpret_cast<float2*>(sP + (3*si)*64);
      sp[lane] = p0; sp[32+lane] = p1; sp[64+lane] = p2;

      // Q = g2 - skew(vsum) * J3n
      float q0x = g20x - (vs1*a2.x - vs2*a1.x);
      float q0y = g20y - (vs1*a2.y - vs2*a1.y);
      float q1x = g21x - (vs2*a0.x - vs0*a2.x);
      float q1y = g21y - (vs2*a0.y - vs0*a2.y);
      float q2x = g22x - (vs0*a1.x - vs1*a0.x);
      float q2y = g22y - (vs0*a1.y - vs1*a0.y);

      // Cholesky C = L L^T
      float l00 = sqrtf(fmaxf(c00, 1e-30f));
      float i00 = 1.f/l00;
      float l10 = c01*i00, l20 = c02*i00;
      float l11 = sqrtf(fmaxf(c11 - l10*l10, 1e-30f));
      float i11 = 1.f/l11;
      float l21 = (c12 - l20*l10)*i11;
      float l22 = sqrtf(fmaxf(c22 - l20*l20 - l21*l21, 1e-30f));
      float i22 = 1.f/l22;

      // Z = L^{-1} Q
      float2 z0, z1, z2;
      z0.x = q0x*i00;                           z0.y = q0y*i00;
      z1.x = (q1x - l10*z0.x)*i11;              z1.y = (q1y - l10*z0.y)*i11;
      z2.x = (q2x - l20*z0.x - l21*z1.x)*i22;   z2.y = (q2y - l20*z0.y - l21*z1.y)*i22;

      float2* sz  = reinterpret_cast<float2*>(sZ  + (3*si)*64);
      float2* szn = reinterpret_cast<float2*>(sZn + (3*si)*64);
      sz[lane]    = z0; sz[32+lane]  = z1; sz[64+lane]  = z2;
      float2 m0, m1, m2;
      m0.x = -z0.x; m0.y = -z0.y;
      m1.x = -z1.x; m1.y = -z1.y;
      m2.x = -z2.x; m2.y = -z2.y;
      szn[lane]   = m0; szn[32+lane] = m1; szn[64+lane] = m2;
    }
    __syncthreads();

    // ---- gram: group g covers k in [g*24, g*24+24) ----
    const float4* s4J = reinterpret_cast<const float4*>(sJ);
    const float4* s4Z = reinterpret_cast<const float4*>(sZ);
    #pragma unroll 4
    for(int kk = 0; kk < 24; kk++){
      int k = g*24 + kk;
      float4 jv = s4J[k*16 + ty];
      float4 zv = s4Z[k*16 + ty];
      const ull* pRow = reinterpret_cast<const ull*>(sP  + k*64 + tx*8);
      const ull* zRow = reinterpret_cast<const ull*>(sZn + k*64 + tx*8);
      ull bp0 = pRow[0], bp1 = pRow[1], bp2 = pRow[2], bp3 = pRow[3];
      ull zp0 = zRow[0], zp1 = zRow[1], zp2 = zRow[2], zp3 = zRow[3];
      ull ad[4], zd[4];
      PK2(ad[0], jv.x, jv.x); PK2(ad[1], jv.y, jv.y);
      PK2(ad[2], jv.z, jv.z); PK2(ad[3], jv.w, jv.w);
      PK2(zd[0], zv.x, zv.x); PK2(zd[1], zv.y, zv.y);
      PK2(zd[2], zv.z, zv.z); PK2(zd[3], zv.w, zv.w);
      #pragma unroll
      for(int i = 0; i < 4; i++){
        FMA2(acc[i][0], ad[i], bp0);
        FMA2(acc[i][1], ad[i], bp1);
        FMA2(acc[i][2], ad[i], bp2);
        FMA2(acc[i][3], ad[i], bp3);
        FMA2(acc[i][0], zd[i], zp0);
        FMA2(acc[i][1], zd[i], zp1);
        FMA2(acc[i][2], zd[i], zp2);
        FMA2(acc[i][3], zd[i], zp3);
      }
    }
  }

  // write this group's 64x64 partial
  ull* outp = reinterpret_cast<ull*>(
      g_part + ((size_t)b*NPART + (size_t)blockIdx.x*2 + g)*DD*DD);
  #pragma unroll
  for(int i = 0; i < 4; i++){
    int row = ty*4 + i;
    #pragma unroll
    for(int j = 0; j < 4; j++)
      outp[row*32 + tx*4 + j] = acc[i][j];
  }
}

// Deterministic reduction of partials.
__global__ void k_reduce(){
  int idx = blockIdx.x*blockDim.x + threadIdx.x;
  if(idx >= BB*DD*DD) return;
  int b = idx >> 12;
  int e = idx & 4095;
  const float* base = g_part + (size_t)b*NPART*4096 + e;
  float s0=0.f, s1=0.f, s2=0.f, s3=0.f;
  #pragma unroll 4
  for(int sp = 0; sp < NPART; sp += 4){
    s0 += base[(size_t)(sp  )*4096];
    s1 += base[(size_t)(sp+1)*4096];
    s2 += base[(size_t)(sp+2)*4096];
    s3 += base[(size_t)(sp+3)*4096];
  }
  g_M[idx] = (s0+s1) + (s2+s3);
}

// Eigenvalues via Householder tridiagonalization + Sturm bisection.
__global__ void k_eig(){
  __shared__ float s[64][65];
  __shared__ float v[64], w[64], dd[64], ee[64], e2[64];
  __shared__ float red[64];
  __shared__ float sc[4];
  __shared__ float bnd[2];
  int b = blockIdx.x;
  int tid = threadIdx.x;
  const float* Mb = g_M + b*4096;
  for(int i = tid; i < 4096; i += 256){
    int r = i >> 6, c = i & 63;
    s[r][c] = 0.5f*(Mb[r*64+c] + Mb[c*64+r]);
  }
  __syncthreads();

  for(int k = 0; k < 62; k++){
    int m = 63 - k;
    if(tid < 64){
      float xi = (tid < m) ? s[k+1+tid][k] : 0.f;
      red[tid] = xi*xi;
    }
    __syncthreads();
    if(tid < 32){
      float val = red[tid] + red[tid+32];
      #pragma unroll
      for(int o = 16; o > 0; o >>= 1) val += __shfl_down_sync(0xffffffffu, val, o);
      if(tid == 0){
        float norm2 = val;
        float x0 = s[k+1][k];
        if(norm2 < 1e-28f){
          sc[0] = x0; sc[1] = 0.f; sc[2] = 0.f;
        } else {
          float alpha = (x0 >= 0.f) ? -sqrtf(norm2) : sqrtf(norm2);
          float v0 = x0 - alpha;
          float vtv = 2.f*(norm2 - alpha*x0);
          sc[0] = alpha; sc[1] = 2.f/vtv; sc[2] = v0;
        }
      }
    }
    __syncthreads();
    float beta = sc[1];
    if(tid == 0) ee[k] = sc[0];
    if(beta != 0.f){
      if(tid < 64){
        v[tid] = (tid < m) ? ((tid == 0) ? sc[2] : s[k+1+tid][k]) : 0.f;
      }
      __syncthreads();
      if(tid < m){
        int i = k+1+tid;
        float acc0 = 0.f, acc1 = 0.f;
        int j = 0;
        for(; j+1 < m; j += 2){
          acc0 = fmaf(s[i][k+1+j], v[j],   acc0);
          acc1 = fmaf(s[i][k+2+j], v[j+1], acc1);
        }
        if(j < m) acc0 = fmaf(s[i][k+1+j], v[j], acc0);
        float p = beta*(acc0 + acc1);
        w[tid] = p;
        red[tid] = p*v[tid];
      } else if(tid < 64){
        red[tid] = 0.f;
      }
      __syncthreads();
      if(tid < 32){
        float val = red[tid] + red[tid+32];
        #pragma unroll
        for(int o = 16; o > 0; o >>= 1) val += __shfl_down_sync(0xffffffffu, val, o);
        if(tid == 0) sc[3] = val;
      }
      __syncthreads();
      if(tid < m){
        float K = 0.5f*beta*sc[3];
        w[tid] = w[tid] - K*v[tid];
      }
      __syncthreads();
      {
        int r = tid & 63, q = tid >> 6;
        if(r < m){
          float vr = v[r], wr = w[r];
          for(int j = q; j < m; j += 4){
            s[k+1+r][k+1+j] -= vr*w[j] + wr*v[j];
          }
        }
      }
      __syncthreads();
    } else {
      __syncthreads();
    }
  }
  if(tid == 0) ee[62] = s[63][62];
  __syncthreads();
  if(tid < 64) dd[tid] = s[tid][tid];
  if(tid < 63) e2[tid] = ee[tid]*ee[tid];
  __syncthreads();

  if(tid < 64){
    float el = (tid > 0)  ? fabsf(ee[tid-1]) : 0.f;
    float er = (tid < 63) ? fabsf(ee[tid])   : 0.f;
    red[tid] = dd[tid] - el - er;
    v[tid]   = dd[tid] + el + er;
  }
  __syncthreads();
  if(tid < 32){
    float lo = fminf(red[tid], red[tid+32]);
    float hi = fmaxf(v[tid],   v[tid+32]);
    #pragma unroll
    for(int o = 16; o > 0; o >>= 1){
      lo = fminf(lo, __shfl_down_sync(0xffffffffu, lo, o));
      hi = fmaxf(hi, __shfl_down_sync(0xffffffffu, hi, o));
    }
    if(tid == 0){ bnd[0] = lo; bnd[1] = hi; }
  }
  __syncthreads();

  float val = 0.f;
  if(tid < 64){
    float lo = bnd[0], hi = bnd[1];
    #pragma unroll 1
    for(int it = 0; it < 34; it++){
      float mid = 0.5f*(lo + hi);
      int cnt = 0;
      float q = dd[0] - mid;
      cnt += (q < 0.f);
      #pragma unroll 1
      for(int i = 1; i < 64; i++){
        float aq = fabsf(q);
        float denom = (aq < 1e-25f) ? ((q < 0.f) ? -1e-25f : 1e-25f) : q;
        q = (dd[i] - mid) - __fdividef(e2[i-1], denom);
        cnt += (q < 0.f);
      }
      if(cnt > tid) hi = mid; else lo = mid;
    }
    float lam = 0.5f*(lo + hi);
    val = (lam > 0.f) ? sqrtf(lam) : 0.f;
  }
  if(tid < 64) red[tid] = val;
  __syncthreads();
  if(tid < 32){
    float sum = red[tid] + red[tid+32];
    #pragma unroll
    for(int o = 16; o > 0; o >>= 1) sum += __shfl_down_sync(0xffffffffu, sum, o);
    if(tid == 0) g_trace[b] = sum;
  }
}

__global__ void k_final(float* out){
  if(threadIdx.x == 0)
    out[0] = 0.25f*(g_trace[0] + g_trace[1] + g_trace[2] + g_trace[3]);
}

extern "C" void kernel_launch(void* const* d_in, const int* in_sizes, int n_in,
                              void* d_out, int out_size){
  const float* x  = (const float*)d_in[0];
  const float* J  = (const float*)d_in[1];
  const int*   e0 = (const int*)d_in[2];
  const int*   e1 = (const int*)d_in[3];
  int E = in_sizes[2];
  float* out = (float*)d_out;

  k_rowptr<<<(E + 255)/256, 256>>>(e0, E);
  k_fused<<<dim3(SPLITX, BB), 256>>>(x, J, e1);
  k_reduce<<<(BB*DD*DD + 255)/256, 256>>>();
  k_eig<<<BB, 256>>>();
  k_final<<<1, 32>>>(out);
}

// round 4
// speedup vs baseline: 1.3040x; 1.3040x over previous
#include <cuda_runtime.h>
#include <math.h>
#include <stdint.h>

#define BB 4
#define NN 25600
#define DD 64
#define RR (3*NN)
#define SPLIT 148
#define NPART SPLIT
#define KT 32

typedef unsigned long long ull;

__device__ float g_P[(size_t)BB*RR*DD];
__device__ float g_Z[(size_t)BB*RR*DD];
__device__ float g_part[(size_t)BB*NPART*DD*DD];
__device__ float g_M[BB*DD*DD];
__device__ float g_td[BB*128];     // per batch: d[64], e[63]
__device__ float g_trace[BB];
__device__ int   g_rowptr[NN+1];

#define PK2(dst, lo, hi) asm("mov.b64 %0, {%1,%2};" : "=l"(dst) : "f"(lo), "f"(hi))
#define UPK2(lo, hi, src) asm("mov.b64 {%0,%1}, %2;" : "=f"(lo), "=f"(hi) : "l"(src))
#define FMA2(acc, a, b) asm("fma.rn.f32x2 %0, %1, %2, %0;" : "+l"(acc) : "l"(a), "l"(b))

// Build CSR row pointers from the lexicographically sorted e0 array.
__global__ void k_rowptr(const int* __restrict__ e0, int E){
  int i = blockIdx.x*blockDim.x + threadIdx.x;
  if(i >= E) return;
  int cur  = e0[i];
  int prev = (i==0) ? -1 : e0[i-1];
  for(int n = prev+1; n <= cur; n++) g_rowptr[n] = i;
  if(i == E-1){
    for(int n = cur+1; n <= NN; n++) g_rowptr[n] = E;
  }
}

// One warp per (batch, node): P = LJ rows, Z = Lc^{-1} BTJ rows.
__global__ void k_phaseA(const float* __restrict__ x, const float* __restrict__ J,
                         const int* __restrict__ e1)
{
  int gw   = (blockIdx.x*blockDim.x + threadIdx.x) >> 5;
  int lane = threadIdx.x & 31;
  if(gw >= BB*NN) return;
  int b = gw / NN;
  int n = gw - b*NN;

  const float* xb = x + (size_t)b*NN*3;
  const float* Jb = J + (size_t)b*RR*DD;
  int rs = g_rowptr[n], re = g_rowptr[n+1];
  float deg = (float)(re - rs);
  float xn0 = xb[3*n], xn1 = xb[3*n+1], xn2 = xb[3*n+2];

  float g10x=0,g10y=0,g11x=0,g11y=0,g12x=0,g12y=0;
  float g20x=0,g20y=0,g21x=0,g21y=0,g22x=0,g22y=0;
  float c00=0,c11=0,c22=0,c01=0,c02=0,c12=0;
  float vs0=0,vs1=0,vs2=0;

  for(int e = rs; e < re; e++){
    int m = e1[e];
    float v0 = xn0 - xb[3*m];
    float v1 = xn1 - xb[3*m+1];
    float v2 = xn2 - xb[3*m+2];
    const float2* Jm = reinterpret_cast<const float2*>(Jb + (size_t)m*192);
    float2 j0 = Jm[lane];
    float2 j1 = Jm[32+lane];
    float2 j2 = Jm[64+lane];
    g10x += j0.x; g10y += j0.y;
    g11x += j1.x; g11y += j1.y;
    g12x += j2.x; g12y += j2.y;
    g20x += v1*j2.x - v2*j1.x;  g20y += v1*j2.y - v2*j1.y;
    g21x += v2*j0.x - v0*j2.x;  g21y += v2*j0.y - v0*j2.y;
    g22x += v0*j1.x - v1*j0.x;  g22y += v0*j1.y - v1*j0.y;
    float vv = v0*v0 + v1*v1 + v2*v2;
    c00 += vv - v0*v0;
    c11 += vv - v1*v1;
    c22 += vv - v2*v2;
    c01 -= v0*v1; c02 -= v0*v2; c12 -= v1*v2;
    vs0 += v0; vs1 += v1; vs2 += v2;
  }

  const float2* Jn = reinterpret_cast<const float2*>(Jb + (size_t)n*192);
  float2 a0 = Jn[lane], a1 = Jn[32+lane], a2 = Jn[64+lane];

  float2* Pp = reinterpret_cast<float2*>(g_P + ((size_t)b*NN + n)*192);
  float2 p0, p1, p2;
  p0.x = 2.f*(deg*a0.x - g10x); p0.y = 2.f*(deg*a0.y - g10y);
  p1.x = 2.f*(deg*a1.x - g11x); p1.y = 2.f*(deg*a1.y - g11y);
  p2.x = 2.f*(deg*a2.x - g12x); p2.y = 2.f*(deg*a2.y - g12y);
  Pp[lane] = p0; Pp[32+lane] = p1; Pp[64+lane] = p2;

  float q0x = g20x - (vs1*a2.x - vs2*a1.x);
  float q0y = g20y - (vs1*a2.y - vs2*a1.y);
  float q1x = g21x - (vs2*a0.x - vs0*a2.x);
  float q1y = g21y - (vs2*a0.y - vs0*a2.y);
  float q2x = g22x - (vs0*a1.x - vs1*a0.x);
  float q2y = g22y - (vs0*a1.y - vs1*a0.y);

  float l00 = sqrtf(fmaxf(c00, 1e-30f));
  float i00 = 1.f/l00;
  float l10 = c01*i00, l20 = c02*i00;
  float l11 = sqrtf(fmaxf(c11 - l10*l10, 1e-30f));
  float i11 = 1.f/l11;
  float l21 = (c12 - l20*l10)*i11;
  float l22 = sqrtf(fmaxf(c22 - l20*l20 - l21*l21, 1e-30f));
  float i22 = 1.f/l22;

  float2 z0, z1, z2;
  z0.x = q0x*i00;                           z0.y = q0y*i00;
  z1.x = (q1x - l10*z0.x)*i11;              z1.y = (q1y - l10*z0.y)*i11;
  z2.x = (q2x - l20*z0.x - l21*z1.x)*i22;   z2.y = (q2y - l20*z0.y - l21*z1.y)*i22;

  float2* Zp = reinterpret_cast<float2*>(g_Z + ((size_t)b*NN + n)*192);
  Zp[lane] = z0; Zp[32+lane] = z1; Zp[64+lane] = z2;
}

// M_partial = sum_rows (J_row (x) P_row - Z_row (x) Z_row).
// 4 k-groups of 64 threads; per-thread 8x8 f32x2 tiles; in-block cross-group
// reduction so each block writes ONE 64x64 partial.
__global__ void __launch_bounds__(256, 1) k_gram(const float* __restrict__ J){
  __shared__ float smem[3*KT*64];
  float* sJ = smem;
  float* sP = smem + KT*64;
  float* sZ = smem + 2*KT*64;
  int b   = blockIdx.y;
  int tid = threadIdx.x;
  int g   = tid >> 6;
  int t   = tid & 63;
  int ty  = t >> 3;
  int tx  = t & 7;

  const float4* gJ = reinterpret_cast<const float4*>(J   + (size_t)b*RR*DD);
  const float4* gP = reinterpret_cast<const float4*>(g_P + (size_t)b*RR*DD);
  const float4* gZ = reinterpret_cast<const float4*>(g_Z + (size_t)b*RR*DD);
  float4* s4J = reinterpret_cast<float4*>(sJ);
  float4* s4P = reinterpret_cast<float4*>(sP);
  float4* s4Z = reinterpret_cast<float4*>(sZ);

  ull acc[8][4];
  #pragma unroll
  for(int i=0;i<8;i++)
    #pragma unroll
    for(int j=0;j<4;j++) acc[i][j] = 0ull;

  const int ntiles = RR/KT;   // 2400
  for(int tt = blockIdx.x; tt < ntiles; tt += SPLIT){
    size_t base4 = (size_t)tt*KT*16;
    __syncthreads();
    #pragma unroll
    for(int i=0;i<2;i++){
      int idx = tid + i*256;
      s4J[idx] = gJ[base4+idx];
      s4P[idx] = gP[base4+idx];
      s4Z[idx] = gZ[base4+idx];
    }
    __syncthreads();
    #pragma unroll
    for(int kk=0;kk<8;kk++){
      int k = g*8 + kk;
      float4 ja = s4J[k*16+ty*2], jb = s4J[k*16+ty*2+1];
      float4 za = s4Z[k*16+ty*2], zb = s4Z[k*16+ty*2+1];
      float4 pa = s4P[k*16+tx*2], pb = s4P[k*16+tx*2+1];
      float4 ca = s4Z[k*16+tx*2], cb = s4Z[k*16+tx*2+1];

      ull ad[8], zd[8], bp[4], zp[4];
      PK2(ad[0], ja.x, ja.x); PK2(ad[1], ja.y, ja.y);
      PK2(ad[2], ja.z, ja.z); PK2(ad[3], ja.w, ja.w);
      PK2(ad[4], jb.x, jb.x); PK2(ad[5], jb.y, jb.y);
      PK2(ad[6], jb.z, jb.z); PK2(ad[7], jb.w, jb.w);
      PK2(zd[0], za.x, za.x); PK2(zd[1], za.y, za.y);
      PK2(zd[2], za.z, za.z); PK2(zd[3], za.w, za.w);
      PK2(zd[4], zb.x, zb.x); PK2(zd[5], zb.y, zb.y);
      PK2(zd[6], zb.z, zb.z); PK2(zd[7], zb.w, zb.w);
      PK2(bp[0], pa.x, pa.y); PK2(bp[1], pa.z, pa.w);
      PK2(bp[2], pb.x, pb.y); PK2(bp[3], pb.z, pb.w);
      float n0 = -ca.x, n1 = -ca.y, n2 = -ca.z, n3 = -ca.w;
      float n4 = -cb.x, n5 = -cb.y, n6 = -cb.z, n7 = -cb.w;
      PK2(zp[0], n0, n1); PK2(zp[1], n2, n3);
      PK2(zp[2], n4, n5); PK2(zp[3], n6, n7);

      #pragma unroll
      for(int ii=0;ii<8;ii++)
        #pragma unroll
        for(int jj=0;jj<4;jj++){
          FMA2(acc[ii][jj], ad[ii], bp[jj]);
          FMA2(acc[ii][jj], zd[ii], zp[jj]);
        }
    }
  }

  // cross-group reduction in shared, then one coalesced partial write
  __syncthreads();
  float2* rb2 = reinterpret_cast<float2*>(smem);
  #pragma unroll 1
  for(int gg = 0; gg < 4; gg++){
    if(g == gg){
      #pragma unroll
      for(int ii=0;ii<8;ii++){
        int row = ty*8 + ii;
        #pragma unroll
        for(int jj=0;jj<4;jj++){
          float lo, hi;
          UPK2(lo, hi, acc[ii][jj]);
          int idx = row*32 + tx*4 + jj;
          if(gg == 0){
            rb2[idx] = make_float2(lo, hi);
          } else {
            float2 o = rb2[idx];
            o.x += lo; o.y += hi;
            rb2[idx] = o;
          }
        }
      }
    }
    __syncthreads();
  }
  float4* outp = reinterpret_cast<float4*>(
      g_part + ((size_t)b*NPART + blockIdx.x)*DD*DD);
  const float4* rb4 = reinterpret_cast<const float4*>(smem);
  #pragma unroll
  for(int i = 0; i < 4; i++)
    outp[tid + i*256] = rb4[tid + i*256];
}

// Deterministic reduction of partials.
__global__ void k_reduce(){
  int idx = blockIdx.x*blockDim.x + threadIdx.x;
  if(idx >= BB*DD*DD) return;
  int b = idx >> 12;
  int e = idx & 4095;
  const float* base = g_part + (size_t)b*NPART*4096 + e;
  float s0=0.f, s1=0.f, s2=0.f, s3=0.f;
  #pragma unroll 4
  for(int sp = 0; sp < NPART; sp += 4){
    s0 += base[(size_t)(sp  )*4096];
    s1 += base[(size_t)(sp+1)*4096];
    s2 += base[(size_t)(sp+2)*4096];
    s3 += base[(size_t)(sp+3)*4096];
  }
  g_M[idx] = (s0+s1) + (s2+s3);
}

// Householder tridiagonalization, ONE WARP per matrix: no block barriers,
// all reductions via shfl, scalar math redundant in all lanes.
__global__ void k_tridiag(){
  __shared__ float s[64][65];
  __shared__ float vv[64], ww[64], ee[64];
  int b = blockIdx.x;
  int lane = threadIdx.x;
  const float* Mb = g_M + b*4096;
  for(int i = lane; i < 4096; i += 32){
    int r = i >> 6, c = i & 63;
    s[r][c] = 0.5f*(Mb[r*64+c] + Mb[c*64+r]);
  }
  __syncwarp();

  int i0 = lane, i1 = lane + 32;
  for(int k = 0; k < 62; k++){
    int m = 63 - k;
    int r0 = k+1+i0; if(r0 > 63) r0 = 63;
    int r1 = k+1+i1; if(r1 > 63) r1 = 63;
    float x0 = (i0 < m) ? s[r0][k] : 0.f;
    float x1 = (i1 < m) ? s[r1][k] : 0.f;
    float n2 = x0*x0 + x1*x1;
    #pragma unroll
    for(int o = 16; o > 0; o >>= 1) n2 += __shfl_xor_sync(0xffffffffu, n2, o);
    float x00 = __shfl_sync(0xffffffffu, x0, 0);
    float alpha, beta;
    if(n2 < 1e-28f){ alpha = x00; beta = 0.f; }
    else {
      alpha = (x00 >= 0.f) ? -sqrtf(n2) : sqrtf(n2);
      beta  = 1.f/(n2 - alpha*x00);
    }
    if(lane == 0) ee[k] = alpha;
    if(beta != 0.f){
      float v_0 = (i0 < m) ? ((i0 == 0) ? (x00 - alpha) : x0) : 0.f;
      float v_1 = (i1 < m) ? x1 : 0.f;
      vv[i0] = v_0; vv[i1] = v_1;
      __syncwarp();
      // p = beta * A' v  (rows i0, i1)
      float p0 = 0.f, p1 = 0.f;
      for(int j = 0; j < m; j++){
        float vj = vv[j];
        p0 = fmaf(s[r0][k+1+j], vj, p0);
        p1 = fmaf(s[r1][k+1+j], vj, p1);
      }
      p0 *= beta; p1 *= beta;
      float ptv = p0*v_0 + p1*v_1;
      #pragma unroll
      for(int o = 16; o > 0; o >>= 1) ptv += __shfl_xor_sync(0xffffffffu, ptv, o);
      float K = 0.5f*beta*ptv;
      float w0 = p0 - K*v_0, w1 = p1 - K*v_1;
      ww[i0] = w0; ww[i1] = w1;
      __syncwarp();
      // A' -= v w^T + w v^T
      bool a0v = (i0 < m), a1v = (i1 < m);
      for(int j = 0; j < m; j++){
        float vj = vv[j], wj = ww[j];
        if(a0v) s[r0][k+1+j] -= v_0*wj + w0*vj;
        if(a1v) s[r1][k+1+j] -= v_1*wj + w1*vj;
      }
      __syncwarp();
    } else {
      __syncwarp();
    }
  }
  if(lane == 0) ee[62] = s[63][62];
  __syncwarp();
  // write d and e
  {
    float d0 = s[i0][i0], d1 = s[i1][i1];
    g_td[b*128 + i0] = d0;
    g_td[b*128 + i1] = d1;
    if(i0 < 63) g_td[b*128 + 64 + i0] = ee[i0];
    if(i1 < 63) g_td[b*128 + 64 + i1] = ee[i1];
  }
}

// 4-way multisection (4 probes per eigenvalue, interval shrinks 5x/round).
__global__ void k_bisect(){
  __shared__ float d[64], e2s[64];
  __shared__ float loA[64], hiA[64];
  __shared__ float bnd[2];
  __shared__ float red[64];
  int b = blockIdx.x;
  int tid = threadIdx.x;
  if(tid < 64) d[tid] = g_td[b*128 + tid];
  if(tid < 63){ float e = g_td[b*128 + 64 + tid]; e2s[tid] = e*e; }
  __syncthreads();
  if(tid < 64){
    float el = (tid > 0)  ? sqrtf(e2s[tid-1]) : 0.f;
    float er = (tid < 63) ? sqrtf(e2s[tid])   : 0.f;
    loA[tid] = d[tid] - el - er;
    hiA[tid] = d[tid] + el + er;
  }
  __syncthreads();
  if(tid < 32){
    float lo = fminf(loA[tid], loA[tid+32]);
    float hi = fmaxf(hiA[tid], hiA[tid+32]);
    #pragma unroll
    for(int o = 16; o > 0; o >>= 1){
      lo = fminf(lo, __shfl_down_sync(0xffffffffu, lo, o));
      hi = fmaxf(hi, __shfl_down_sync(0xffffffffu, hi, o));
    }
    if(tid == 0){ bnd[0] = lo; bnd[1] = hi; }
  }
  __syncthreads();

  int j = tid >> 2;          // eigenvalue index
  int t = tid & 3;           // probe index
  int wl = tid & 31;         // lane in warp
  unsigned base = wl & ~3u;
  float lo = bnd[0], hi = bnd[1];

  #pragma unroll 1
  for(int r = 0; r < 10; r++){
    float mid = lo + (hi - lo)*0.2f*(float)(t+1);
    int cnt = 0;
    float q = d[0] - mid;
    cnt += (q < 0.f);
    #pragma unroll 1
    for(int i = 1; i < 64; i++){
      float aq = fabsf(q);
      float denom = (aq < 1e-25f) ? ((q < 0.f) ? -1e-25f : 1e-25f) : q;
      q = (d[i] - mid) - __fdividef(e2s[i-1], denom);
      cnt += (q < 0.f);
    }
    int less = (cnt > j);
    #pragma unroll
    for(int s2 = 0; s2 < 4; s2++){
      float ms = __shfl_sync(0xffffffffu, mid,  base + s2);
      int   ls = __shfl_sync(0xffffffffu, less, base + s2);
      if(ls) hi = fminf(hi, ms); else lo = fmaxf(lo, ms);
    }
  }

  float lam = 0.5f*(lo + hi);
  float val = (t == 0 && lam > 0.f) ? sqrtf(lam) : 0.f;
  // sum the t==0 contributions
  #pragma unroll
  for(int o = 16; o > 0; o >>= 1) val += __shfl_down_sync(0xffffffffu, val, o);
  if(wl == 0) red[tid >> 5] = val;
  __syncthreads();
  if(tid == 0){
    float sum = 0.f;
    #pragma unroll
    for(int w = 0; w < 8; w++) sum += red[w];
    g_trace[b] = sum;
  }
}

__global__ void k_final(float* out){
  if(threadIdx.x == 0)
    out[0] = 0.25f*(g_trace[0] + g_trace[1] + g_trace[2] + g_trace[3]);
}

extern "C" void kernel_launch(void* const* d_in, const int* in_sizes, int n_in,
                              void* d_out, int out_size){
  const float* x  = (const float*)d_in[0];
  const float* J  = (const float*)d_in[1];
  const int*   e0 = (const int*)d_in[2];
  const int*   e1 = (const int*)d_in[3];
  int E = in_sizes[2];
  float* out = (float*)d_out;

  k_rowptr<<<(E + 255)/256, 256>>>(e0, E);
  k_phaseA<<<(BB*NN)/8, 256>>>(x, J, e1);
  k_gram<<<dim3(SPLIT, BB), 256>>>(J);
  k_reduce<<<(BB*DD*DD + 255)/256, 256>>>();
  k_tridiag<<<BB, 32>>>();
  k_bisect<<<BB, 256>>>();
  k_final<<<1, 32>>>(out);
}

// round 5
// speedup vs baseline: 1.3178x; 1.0106x over previous
#include <cuda_runtime.h>
#include <math.h>
#include <stdint.h>

#define BB 4
#define NN 25600
#define DD 64
#define RR (3*NN)
#define SPLIT 148
#define NPART SPLIT
#define KT 32

typedef unsigned long long ull;

__device__ float g_P[(size_t)BB*RR*DD];
__device__ float g_Z[(size_t)BB*RR*DD];
__device__ float g_part[(size_t)BB*NPART*DD*DD];
__device__ float g_part2[BB*4*DD*DD];
__device__ float g_M[BB*DD*DD];
__device__ float g_td[BB*128];     // per batch: d[64], e[63]
__device__ float g_trace[BB];
__device__ int   g_rowptr[NN+1];

#define PK2(dst, lo, hi) asm("mov.b64 %0, {%1,%2};" : "=l"(dst) : "f"(lo), "f"(hi))
#define UPK2(lo, hi, src) asm("mov.b64 {%0,%1}, %2;" : "=f"(lo), "=f"(hi) : "l"(src))
#define FMA2(acc, a, b) asm("fma.rn.f32x2 %0, %1, %2, %0;" : "+l"(acc) : "l"(a), "l"(b))

// Build CSR row pointers from the lexicographically sorted e0 array.
__global__ void k_rowptr(const int* __restrict__ e0, int E){
  int i = blockIdx.x*blockDim.x + threadIdx.x;
  if(i >= E) return;
  int cur  = e0[i];
  int prev = (i==0) ? -1 : e0[i-1];
  for(int n = prev+1; n <= cur; n++) g_rowptr[n] = i;
  if(i == E-1){
    for(int n = cur+1; n <= NN; n++) g_rowptr[n] = E;
  }
}

// One warp per (batch, node): P = LJ rows, Z = Lc^{-1} BTJ rows.
__global__ void k_phaseA(const float* __restrict__ x, const float* __restrict__ J,
                         const int* __restrict__ e1)
{
  int gw   = (blockIdx.x*blockDim.x + threadIdx.x) >> 5;
  int lane = threadIdx.x & 31;
  if(gw >= BB*NN) return;
  int b = gw / NN;
  int n = gw - b*NN;

  const float* xb = x + (size_t)b*NN*3;
  const float* Jb = J + (size_t)b*RR*DD;
  int rs = g_rowptr[n], re = g_rowptr[n+1];
  float deg = (float)(re - rs);
  float xn0 = xb[3*n], xn1 = xb[3*n+1], xn2 = xb[3*n+2];

  float g10x=0,g10y=0,g11x=0,g11y=0,g12x=0,g12y=0;
  float g20x=0,g20y=0,g21x=0,g21y=0,g22x=0,g22y=0;
  float c00=0,c11=0,c22=0,c01=0,c02=0,c12=0;
  float vs0=0,vs1=0,vs2=0;

  for(int e = rs; e < re; e++){
    int m = e1[e];
    float v0 = xn0 - xb[3*m];
    float v1 = xn1 - xb[3*m+1];
    float v2 = xn2 - xb[3*m+2];
    const float2* Jm = reinterpret_cast<const float2*>(Jb + (size_t)m*192);
    float2 j0 = Jm[lane];
    float2 j1 = Jm[32+lane];
    float2 j2 = Jm[64+lane];
    g10x += j0.x; g10y += j0.y;
    g11x += j1.x; g11y += j1.y;
    g12x += j2.x; g12y += j2.y;
    g20x += v1*j2.x - v2*j1.x;  g20y += v1*j2.y - v2*j1.y;
    g21x += v2*j0.x - v0*j2.x;  g21y += v2*j0.y - v0*j2.y;
    g22x += v0*j1.x - v1*j0.x;  g22y += v0*j1.y - v1*j0.y;
    float vv = v0*v0 + v1*v1 + v2*v2;
    c00 += vv - v0*v0;
    c11 += vv - v1*v1;
    c22 += vv - v2*v2;
    c01 -= v0*v1; c02 -= v0*v2; c12 -= v1*v2;
    vs0 += v0; vs1 += v1; vs2 += v2;
  }

  const float2* Jn = reinterpret_cast<const float2*>(Jb + (size_t)n*192);
  float2 a0 = Jn[lane], a1 = Jn[32+lane], a2 = Jn[64+lane];

  float2* Pp = reinterpret_cast<float2*>(g_P + ((size_t)b*NN + n)*192);
  float2 p0, p1, p2;
  p0.x = 2.f*(deg*a0.x - g10x); p0.y = 2.f*(deg*a0.y - g10y);
  p1.x = 2.f*(deg*a1.x - g11x); p1.y = 2.f*(deg*a1.y - g11y);
  p2.x = 2.f*(deg*a2.x - g12x); p2.y = 2.f*(deg*a2.y - g12y);
  Pp[lane] = p0; Pp[32+lane] = p1; Pp[64+lane] = p2;

  float q0x = g20x - (vs1*a2.x - vs2*a1.x);
  float q0y = g20y - (vs1*a2.y - vs2*a1.y);
  float q1x = g21x - (vs2*a0.x - vs0*a2.x);
  float q1y = g21y - (vs2*a0.y - vs0*a2.y);
  float q2x = g22x - (vs0*a1.x - vs1*a0.x);
  float q2y = g22y - (vs0*a1.y - vs1*a0.y);

  float l00 = sqrtf(fmaxf(c00, 1e-30f));
  float i00 = 1.f/l00;
  float l10 = c01*i00, l20 = c02*i00;
  float l11 = sqrtf(fmaxf(c11 - l10*l10, 1e-30f));
  float i11 = 1.f/l11;
  float l21 = (c12 - l20*l10)*i11;
  float l22 = sqrtf(fmaxf(c22 - l20*l20 - l21*l21, 1e-30f));
  float i22 = 1.f/l22;

  float2 z0, z1, z2;
  z0.x = q0x*i00;                           z0.y = q0y*i00;
  z1.x = (q1x - l10*z0.x)*i11;              z1.y = (q1y - l10*z0.y)*i11;
  z2.x = (q2x - l20*z0.x - l21*z1.x)*i22;   z2.y = (q2y - l20*z0.y - l21*z1.y)*i22;

  float2* Zp = reinterpret_cast<float2*>(g_Z + ((size_t)b*NN + n)*192);
  Zp[lane] = z0; Zp[32+lane] = z1; Zp[64+lane] = z2;
}

// M_partial = sum_rows (J_row (x) P_row - Z_row (x) Z_row).
__global__ void __launch_bounds__(256, 1) k_gram(const float* __restrict__ J){
  __shared__ float smem[3*KT*64];
  float* sJ = smem;
  float* sP = smem + KT*64;
  float* sZ = smem + 2*KT*64;
  int b   = blockIdx.y;
  int tid = threadIdx.x;
  int g   = tid >> 6;
  int t   = tid & 63;
  int ty  = t >> 3;
  int tx  = t & 7;

  const float4* gJ = reinterpret_cast<const float4*>(J   + (size_t)b*RR*DD);
  const float4* gP = reinterpret_cast<const float4*>(g_P + (size_t)b*RR*DD);
  const float4* gZ = reinterpret_cast<const float4*>(g_Z + (size_t)b*RR*DD);
  float4* s4J = reinterpret_cast<float4*>(sJ);
  float4* s4P = reinterpret_cast<float4*>(sP);
  float4* s4Z = reinterpret_cast<float4*>(sZ);

  ull acc[8][4];
  #pragma unroll
  for(int i=0;i<8;i++)
    #pragma unroll
    for(int j=0;j<4;j++) acc[i][j] = 0ull;

  const int ntiles = RR/KT;   // 2400
  for(int tt = blockIdx.x; tt < ntiles; tt += SPLIT){
    size_t base4 = (size_t)tt*KT*16;
    __syncthreads();
    #pragma unroll
    for(int i=0;i<2;i++){
      int idx = tid + i*256;
      s4J[idx] = gJ[base4+idx];
      s4P[idx] = gP[base4+idx];
      s4Z[idx] = gZ[base4+idx];
    }
    __syncthreads();
    #pragma unroll
    for(int kk=0;kk<8;kk++){
      int k = g*8 + kk;
      float4 ja = s4J[k*16+ty*2], jb = s4J[k*16+ty*2+1];
      float4 za = s4Z[k*16+ty*2], zb = s4Z[k*16+ty*2+1];
      float4 pa = s4P[k*16+tx*2], pb = s4P[k*16+tx*2+1];
      float4 ca = s4Z[k*16+tx*2], cb = s4Z[k*16+tx*2+1];

      ull ad[8], zd[8], bp[4], zp[4];
      PK2(ad[0], ja.x, ja.x); PK2(ad[1], ja.y, ja.y);
      PK2(ad[2], ja.z, ja.z); PK2(ad[3], ja.w, ja.w);
      PK2(ad[4], jb.x, jb.x); PK2(ad[5], jb.y, jb.y);
      PK2(ad[6], jb.z, jb.z); PK2(ad[7], jb.w, jb.w);
      PK2(zd[0], za.x, za.x); PK2(zd[1], za.y, za.y);
      PK2(zd[2], za.z, za.z); PK2(zd[3], za.w, za.w);
      PK2(zd[4], zb.x, zb.x); PK2(zd[5], zb.y, zb.y);
      PK2(zd[6], zb.z, zb.z); PK2(zd[7], zb.w, zb.w);
      PK2(bp[0], pa.x, pa.y); PK2(bp[1], pa.z, pa.w);
      PK2(bp[2], pb.x, pb.y); PK2(bp[3], pb.z, pb.w);
      float n0 = -ca.x, n1 = -ca.y, n2 = -ca.z, n3 = -ca.w;
      float n4 = -cb.x, n5 = -cb.y, n6 = -cb.z, n7 = -cb.w;
      PK2(zp[0], n0, n1); PK2(zp[1], n2, n3);
      PK2(zp[2], n4, n5); PK2(zp[3], n6, n7);

      #pragma unroll
      for(int ii=0;ii<8;ii++)
        #pragma unroll
        for(int jj=0;jj<4;jj++){
          FMA2(acc[ii][jj], ad[ii], bp[jj]);
          FMA2(acc[ii][jj], zd[ii], zp[jj]);
        }
    }
  }

  __syncthreads();
  float2* rb2 = reinterpret_cast<float2*>(smem);
  #pragma unroll 1
  for(int gg = 0; gg < 4; gg++){
    if(g == gg){
      #pragma unroll
      for(int ii=0;ii<8;ii++){
        int row = ty*8 + ii;
        #pragma unroll
        for(int jj=0;jj<4;jj++){
          float lo, hi;
          UPK2(lo, hi, acc[ii][jj]);
          int idx = row*32 + tx*4 + jj;
          if(gg == 0){
            rb2[idx] = make_float2(lo, hi);
          } else {
            float2 o = rb2[idx];
            o.x += lo; o.y += hi;
            rb2[idx] = o;
          }
        }
      }
    }
    __syncthreads();
  }
  float4* outp = reinterpret_cast<float4*>(
      g_part + ((size_t)b*NPART + blockIdx.x)*DD*DD);
  const float4* rb4 = reinterpret_cast<const float4*>(smem);
  #pragma unroll
  for(int i = 0; i < 4; i++)
    outp[tid + i*256] = rb4[tid + i*256];
}

// Two-stage deterministic reduction of the 148 partials per batch.
__global__ void k_reduce1(){
  int elem = blockIdx.x*256 + threadIdx.x;    // 0..4095
  int grp  = blockIdx.y;                      // 0..3 (37 partials each)
  int b    = blockIdx.z;
  const float* base = g_part + (size_t)b*NPART*4096 + elem;
  int s = grp*37;
  float a0=0.f, a1=0.f, a2=0.f, a3=0.f;
  #pragma unroll
  for(int i = 0; i < 36; i += 4){
    a0 += base[(size_t)(s+i  )*4096];
    a1 += base[(size_t)(s+i+1)*4096];
    a2 += base[(size_t)(s+i+2)*4096];
    a3 += base[(size_t)(s+i+3)*4096];
  }
  a0 += base[(size_t)(s+36)*4096];
  g_part2[((b*4 + grp)*4096) + elem] = (a0+a1) + (a2+a3);
}

__global__ void k_reduce2(){
  int elem = blockIdx.x*256 + threadIdx.x;
  int b    = blockIdx.y;
  float v = g_part2[(b*4+0)*4096 + elem]
          + g_part2[(b*4+1)*4096 + elem]
          + g_part2[(b*4+2)*4096 + elem]
          + g_part2[(b*4+3)*4096 + elem];
  g_M[b*4096 + elem] = v;
}

// Householder tridiagonalization, one warp per matrix.
// All inner loops have 16-multiple trip counts (zero-padded) so ptxas fully
// unrolls and batches the LDS (MLP hides the 29-cyc latency).
__global__ void k_tridiag(){
  __shared__ float s[64][81];                 // zero-padded columns 64..80
  __shared__ float vv[64], ww[64], ee[64];
  int b = blockIdx.x;
  int lane = threadIdx.x;

  float* sflat = &s[0][0];
  for(int i = lane; i < 64*81; i += 32) sflat[i] = 0.f;
  __syncwarp();
  const float* Mb = g_M + b*4096;
  for(int i = lane; i < 4096; i += 32){
    int r = i >> 6, c = i & 63;
    s[r][c] = 0.5f*(Mb[r*64+c] + Mb[c*64+r]);
  }
  __syncwarp();

  // ---- phase 1: k = 0..30 (m = 63-k >= 33); lane owns rows k+1+lane, k+33+lane ----
  for(int k = 0; k < 31; k++){
    int m = 63 - k;
    int mm = (m + 15) & ~15;                  // 48 or 64
    int r0 = k + 1 + lane;                    // always a valid trailing row
    bool a1 = (lane + 32 < m);
    int r1v = r0 + 32;
    int r1 = a1 ? r1v : 63;                   // clamped read-only row for inactive lanes
    float x0 = s[r0][k];
    float x1 = a1 ? s[r1v][k] : 0.f;
    float n2 = x0*x0 + x1*x1;
    #pragma unroll
    for(int o = 16; o > 0; o >>= 1) n2 += __shfl_xor_sync(0xffffffffu, n2, o);
    float x00 = __shfl_sync(0xffffffffu, x0, 0);
    float alpha, beta;
    if(n2 < 1e-28f){ alpha = x00; beta = 0.f; }
    else {
      alpha = (x00 >= 0.f) ? -sqrtf(n2) : sqrtf(n2);
      beta  = 1.f/(n2 - alpha*x00);
    }
    if(lane == 0) ee[k] = alpha;
    if(beta != 0.f){
      float v0 = (lane == 0) ? (x00 - alpha) : x0;
      float v1 = a1 ? x1 : 0.f;
      vv[lane] = v0; vv[lane+32] = v1;
      __syncwarp();
      const float* row0 = &s[r0][k+1];
      const float* row1 = &s[r1][k+1];
      float p0 = 0.f, p1 = 0.f;
      for(int jb = 0; jb < mm; jb += 16){
        #pragma unroll
        for(int u = 0; u < 16; u++){
          float vj = vv[jb+u];
          p0 = fmaf(row0[jb+u], vj, p0);
          p1 = fmaf(row1[jb+u], vj, p1);
        }
      }
      p0 *= beta; p1 *= beta;
      float ptv = p0*v0 + p1*v1;              // p1 garbage for inactive lanes, v1=0
      #pragma unroll
      for(int o = 16; o > 0; o >>= 1) ptv += __shfl_xor_sync(0xffffffffu, ptv, o);
      float K = 0.5f*beta*ptv;
      float w0 = p0 - K*v0;
      float w1 = a1 ? (p1 - K*v1) : 0.f;
      ww[lane] = w0; ww[lane+32] = w1;
      __syncwarp();
      float* wr0 = &s[r0][k+1];
      for(int jb = 0; jb < mm; jb += 16){
        #pragma unroll
        for(int u = 0; u < 16; u++){
          int j = jb+u;
          float vj = vv[j], wj = ww[j];
          float tval = wr0[j];
          tval = fmaf(-v0, wj, tval);
          tval = fmaf(-w0, vj, tval);
          wr0[j] = tval;
        }
      }
      if(a1){
        float* wr1 = &s[r1v][k+1];
        for(int jb = 0; jb < mm; jb += 16){
          #pragma unroll
          for(int u = 0; u < 16; u++){
            int j = jb+u;
            float vj = vv[j], wj = ww[j];
            float tval = wr1[j];
            tval = fmaf(-v1, wj, tval);
            tval = fmaf(-w1, vj, tval);
            wr1[j] = tval;
          }
        }
      }
      __syncwarp();
    }
  }

  // ---- phase 2: k = 31..61 (m <= 32); lane owns at most one row ----
  for(int k = 31; k < 62; k++){
    int m = 63 - k;
    int mm = (m + 15) & ~15;                  // 16 or 32
    bool a0 = (lane < m);
    int r0v = k + 1 + lane;
    int r0 = a0 ? r0v : 63;
    float x0 = a0 ? s[r0v][k] : 0.f;
    float n2 = x0*x0;
    #pragma unroll
    for(int o = 16; o > 0; o >>= 1) n2 += __shfl_xor_sync(0xffffffffu, n2, o);
    float x00 = __shfl_sync(0xffffffffu, x0, 0);
    float alpha, beta;
    if(n2 < 1e-28f){ alpha = x00; beta = 0.f; }
    else {
      alpha = (x00 >= 0.f) ? -sqrtf(n2) : sqrtf(n2);
      beta  = 1.f/(n2 - alpha*x00);
    }
    if(lane == 0) ee[k] = alpha;
    if(beta != 0.f){
      float v0 = a0 ? ((lane == 0) ? (x00 - alpha) : x0) : 0.f;
      vv[lane] = v0;
      __syncwarp();
      const float* row0 = &s[r0][k+1];
      float p0 = 0.f;
      for(int jb = 0; jb < mm; jb += 16){
        #pragma unroll
        for(int u = 0; u < 16; u++)
          p0 = fmaf(row0[jb+u], vv[jb+u], p0);
      }
      p0 *= beta;
      float ptv = p0*v0;
      #pragma unroll
      for(int o = 16; o > 0; o >>= 1) ptv += __shfl_xor_sync(0xffffffffu, ptv, o);
      float K = 0.5f*beta*ptv;
      float w0 = a0 ? (p0 - K*v0) : 0.f;
      ww[lane] = w0;
      __syncwarp();
      if(a0){
        float* wr0 = &s[r0v][k+1];
        for(int jb = 0; jb < mm; jb += 16){
          #pragma unroll
          for(int u = 0; u < 16; u++){
            int j = jb+u;
            float tval = wr0[j];
            tval = fmaf(-v0, ww[j], tval);
            tval = fmaf(-w0, vv[j], tval);
            wr0[j] = tval;
          }
        }
      }
      __syncwarp();
    }
  }

  if(lane == 0) ee[62] = s[63][62];
  __syncwarp();
  g_td[b*128 + lane]      = s[lane][lane];
  g_td[b*128 + lane + 32] = s[lane+32][lane+32];
  if(lane < 31) g_td[b*128 + 64 + lane] = ee[lane];
  g_td[b*128 + 64 + 31 + lane] = ee[31 + lane];
}

// 4-way multisection (4 probes per eigenvalue, interval shrinks 5x/round).
__global__ void k_bisect(){
  __shared__ float d[64], e2s[64];
  __shared__ float loA[64], hiA[64];
  __shared__ float bnd[2];
  __shared__ float red[64];
  int b = blockIdx.x;
  int tid = threadIdx.x;
  if(tid < 64) d[tid] = g_td[b*128 + tid];
  if(tid < 63){ float e = g_td[b*128 + 64 + tid]; e2s[tid] = e*e; }
  __syncthreads();
  if(tid < 64){
    float el = (tid > 0)  ? sqrtf(e2s[tid-1]) : 0.f;
    float er = (tid < 63) ? sqrtf(e2s[tid])   : 0.f;
    loA[tid] = d[tid] - el - er;
    hiA[tid] = d[tid] + el + er;
  }
  __syncthreads();
  if(tid < 32){
    float lo = fminf(loA[tid], loA[tid+32]);
    float hi = fmaxf(hiA[tid], hiA[tid+32]);
    #pragma unroll
    for(int o = 16; o > 0; o >>= 1){
      lo = fminf(lo, __shfl_down_sync(0xffffffffu, lo, o));
      hi = fmaxf(hi, __shfl_down_sync(0xffffffffu, hi, o));
    }
    if(tid == 0){ bnd[0] = lo; bnd[1] = hi; }
  }
  __syncthreads();

  int j = tid >> 2;
  int t = tid & 3;
  int wl = tid & 31;
  unsigned base = wl & ~3u;
  float lo = bnd[0], hi = bnd[1];

  #pragma unroll 1
  for(int r = 0; r < 10; r++){
    float mid = lo + (hi - lo)*0.2f*(float)(t+1);
    int cnt = 0;
    float q = d[0] - mid;
    cnt += (q < 0.f);
    #pragma unroll 1
    for(int i = 1; i < 64; i++){
      float aq = fabsf(q);
      float denom = (aq < 1e-25f) ? ((q < 0.f) ? -1e-25f : 1e-25f) : q;
      q = (d[i] - mid) - __fdividef(e2s[i-1], denom);
      cnt += (q < 0.f);
    }
    int less = (cnt > j);
    #pragma unroll
    for(int s2 = 0; s2 < 4; s2++){
      float ms = __shfl_sync(0xffffffffu, mid,  base + s2);
      int   ls = __shfl_sync(0xffffffffu, less, base + s2);
      if(ls) hi = fminf(hi, ms); else lo = fmaxf(lo, ms);
    }
  }

  float lam = 0.5f*(lo + hi);
  float val = (t == 0 && lam > 0.f) ? sqrtf(lam) : 0.f;
  #pragma unroll
  for(int o = 16; o > 0; o >>= 1) val += __shfl_down_sync(0xffffffffu, val, o);
  if(wl == 0) red[tid >> 5] = val;
  __syncthreads();
  if(tid == 0){
    float sum = 0.f;
    #pragma unroll
    for(int w = 0; w < 8; w++) sum += red[w];
    g_trace[b] = sum;
  }
}

__global__ void k_final(float* out){
  if(threadIdx.x == 0)
    out[0] = 0.25f*(g_trace[0] + g_trace[1] + g_trace[2] + g_trace[3]);
}

extern "C" void kernel_launch(void* const* d_in, const int* in_sizes, int n_in,
                              void* d_out, int out_size){
  const float* x  = (const float*)d_in[0];
  const float* J  = (const float*)d_in[1];
  const int*   e0 = (const int*)d_in[2];
  const int*   e1 = (const int*)d_in[3];
  int E = in_sizes[2];
  float* out = (float*)d_out;

  k_rowptr<<<(E + 255)/256, 256>>>(e0, E);
  k_phaseA<<<(BB*NN)/8, 256>>>(x, J, e1);
  k_gram<<<dim3(SPLIT, BB), 256>>>(J);
  k_reduce1<<<dim3(16, 4, BB), 256>>>();
  k_reduce2<<<dim3(16, BB), 256>>>();
  k_tridiag<<<BB, 32>>>();
  k_bisect<<<BB, 256>>>();
  k_final<<<1, 32>>>(out);
}

// round 6
// speedup vs baseline: 1.5369x; 1.1663x over previous
#include <cuda_runtime.h>
#include <math.h>
#include <stdint.h>

#define BB 4
#define NN 25600
#define DD 64
#define RR (3*NN)
#define SPLIT 148
#define NPART SPLIT
#define KT 32

typedef unsigned long long ull;

__device__ float g_P[(size_t)BB*RR*DD];
__device__ float g_Z[(size_t)BB*RR*DD];
__device__ float g_part[(size_t)BB*NPART*DD*DD];
__device__ float g_part2[BB*4*DD*DD];
__device__ float g_M[BB*DD*DD];
__device__ float g_td[BB*128];     // per batch: d[64], e[63]
__device__ float g_trace[BB];
__device__ int   g_rowptr[NN+1];

#define PK2(dst, lo, hi) asm("mov.b64 %0, {%1,%2};" : "=l"(dst) : "f"(lo), "f"(hi))
#define UPK2(lo, hi, src) asm("mov.b64 {%0,%1}, %2;" : "=f"(lo), "=f"(hi) : "l"(src))
#define FMA2(acc, a, b) asm("fma.rn.f32x2 %0, %1, %2, %0;" : "+l"(acc) : "l"(a), "l"(b))

// Build CSR row pointers from the lexicographically sorted e0 array.
__global__ void k_rowptr(const int* __restrict__ e0, int E){
  int i = blockIdx.x*blockDim.x + threadIdx.x;
  if(i >= E) return;
  int cur  = e0[i];
  int prev = (i==0) ? -1 : e0[i-1];
  for(int n = prev+1; n <= cur; n++) g_rowptr[n] = i;
  if(i == E-1){
    for(int n = cur+1; n <= NN; n++) g_rowptr[n] = E;
  }
}

// One warp per (batch, node): P = LJ rows, Z = Lc^{-1} BTJ rows.
// boff selects the batch pair (launched twice so slot-4 ncu capture hits k_gram).
__global__ void k_phaseA(const float* __restrict__ x, const float* __restrict__ J,
                         const int* __restrict__ e1, int boff)
{
  int gw   = (blockIdx.x*blockDim.x + threadIdx.x) >> 5;
  int lane = threadIdx.x & 31;
  if(gw >= 2*NN) return;
  int b = boff + gw / NN;
  int n = gw % NN;

  const float* xb = x + (size_t)b*NN*3;
  const float* Jb = J + (size_t)b*RR*DD;
  int rs = g_rowptr[n], re = g_rowptr[n+1];
  float deg = (float)(re - rs);
  float xn0 = xb[3*n], xn1 = xb[3*n+1], xn2 = xb[3*n+2];

  float g10x=0,g10y=0,g11x=0,g11y=0,g12x=0,g12y=0;
  float g20x=0,g20y=0,g21x=0,g21y=0,g22x=0,g22y=0;
  float c00=0,c11=0,c22=0,c01=0,c02=0,c12=0;
  float vs0=0,vs1=0,vs2=0;

  for(int e = rs; e < re; e++){
    int m = e1[e];
    float v0 = xn0 - xb[3*m];
    float v1 = xn1 - xb[3*m+1];
    float v2 = xn2 - xb[3*m+2];
    const float2* Jm = reinterpret_cast<const float2*>(Jb + (size_t)m*192);
    float2 j0 = Jm[lane];
    float2 j1 = Jm[32+lane];
    float2 j2 = Jm[64+lane];
    g10x += j0.x; g10y += j0.y;
    g11x += j1.x; g11y += j1.y;
    g12x += j2.x; g12y += j2.y;
    g20x += v1*j2.x - v2*j1.x;  g20y += v1*j2.y - v2*j1.y;
    g21x += v2*j0.x - v0*j2.x;  g21y += v2*j0.y - v0*j2.y;
    g22x += v0*j1.x - v1*j0.x;  g22y += v0*j1.y - v1*j0.y;
    float vv = v0*v0 + v1*v1 + v2*v2;
    c00 += vv - v0*v0;
    c11 += vv - v1*v1;
    c22 += vv - v2*v2;
    c01 -= v0*v1; c02 -= v0*v2; c12 -= v1*v2;
    vs0 += v0; vs1 += v1; vs2 += v2;
  }

  const float2* Jn = reinterpret_cast<const float2*>(Jb + (size_t)n*192);
  float2 a0 = Jn[lane], a1 = Jn[32+lane], a2 = Jn[64+lane];

  float2* Pp = reinterpret_cast<float2*>(g_P + ((size_t)b*NN + n)*192);
  float2 p0, p1, p2;
  p0.x = 2.f*(deg*a0.x - g10x); p0.y = 2.f*(deg*a0.y - g10y);
  p1.x = 2.f*(deg*a1.x - g11x); p1.y = 2.f*(deg*a1.y - g11y);
  p2.x = 2.f*(deg*a2.x - g12x); p2.y = 2.f*(deg*a2.y - g12y);
  Pp[lane] = p0; Pp[32+lane] = p1; Pp[64+lane] = p2;

  float q0x = g20x - (vs1*a2.x - vs2*a1.x);
  float q0y = g20y - (vs1*a2.y - vs2*a1.y);
  float q1x = g21x - (vs2*a0.x - vs0*a2.x);
  float q1y = g21y - (vs2*a0.y - vs0*a2.y);
  float q2x = g22x - (vs0*a1.x - vs1*a0.x);
  float q2y = g22y - (vs0*a1.y - vs1*a0.y);

  float l00 = sqrtf(fmaxf(c00, 1e-30f));
  float i00 = 1.f/l00;
  float l10 = c01*i00, l20 = c02*i00;
  float l11 = sqrtf(fmaxf(c11 - l10*l10, 1e-30f));
  float i11 = 1.f/l11;
  float l21 = (c12 - l20*l10)*i11;
  float l22 = sqrtf(fmaxf(c22 - l20*l20 - l21*l21, 1e-30f));
  float i22 = 1.f/l22;

  float2 z0, z1, z2;
  z0.x = q0x*i00;                           z0.y = q0y*i00;
  z1.x = (q1x - l10*z0.x)*i11;              z1.y = (q1y - l10*z0.y)*i11;
  z2.x = (q2x - l20*z0.x - l21*z1.x)*i22;   z2.y = (q2y - l20*z0.y - l21*z1.y)*i22;

  float2* Zp = reinterpret_cast<float2*>(g_Z + ((size_t)b*NN + n)*192);
  Zp[lane] = z0; Zp[32+lane] = z1; Zp[64+lane] = z2;
}

// M_partial = sum_rows (J_row (x) P_row - Z_row (x) Z_row).
__global__ void __launch_bounds__(256, 1) k_gram(const float* __restrict__ J){
  __shared__ float smem[3*KT*64];
  float* sJ = smem;
  float* sP = smem + KT*64;
  float* sZ = smem + 2*KT*64;
  int b   = blockIdx.y;
  int tid = threadIdx.x;
  int g   = tid >> 6;
  int t   = tid & 63;
  int ty  = t >> 3;
  int tx  = t & 7;

  const float4* gJ = reinterpret_cast<const float4*>(J   + (size_t)b*RR*DD);
  const float4* gP = reinterpret_cast<const float4*>(g_P + (size_t)b*RR*DD);
  const float4* gZ = reinterpret_cast<const float4*>(g_Z + (size_t)b*RR*DD);
  float4* s4J = reinterpret_cast<float4*>(sJ);
  float4* s4P = reinterpret_cast<float4*>(sP);
  float4* s4Z = reinterpret_cast<float4*>(sZ);

  ull acc[8][4];
  #pragma unroll
  for(int i=0;i<8;i++)
    #pragma unroll
    for(int j=0;j<4;j++) acc[i][j] = 0ull;

  const int ntiles = RR/KT;   // 2400
  for(int tt = blockIdx.x; tt < ntiles; tt += SPLIT){
    size_t base4 = (size_t)tt*KT*16;
    __syncthreads();
    #pragma unroll
    for(int i=0;i<2;i++){
      int idx = tid + i*256;
      s4J[idx] = gJ[base4+idx];
      s4P[idx] = gP[base4+idx];
      s4Z[idx] = gZ[base4+idx];
    }
    __syncthreads();
    #pragma unroll
    for(int kk=0;kk<8;kk++){
      int k = g*8 + kk;
      float4 ja = s4J[k*16+ty*2], jb = s4J[k*16+ty*2+1];
      float4 za = s4Z[k*16+ty*2], zb = s4Z[k*16+ty*2+1];
      float4 pa = s4P[k*16+tx*2], pb = s4P[k*16+tx*2+1];
      float4 ca = s4Z[k*16+tx*2], cb = s4Z[k*16+tx*2+1];

      ull ad[8], zd[8], bp[4], zp[4];
      PK2(ad[0], ja.x, ja.x); PK2(ad[1], ja.y, ja.y);
      PK2(ad[2], ja.z, ja.z); PK2(ad[3], ja.w, ja.w);
      PK2(ad[4], jb.x, jb.x); PK2(ad[5], jb.y, jb.y);
      PK2(ad[6], jb.z, jb.z); PK2(ad[7], jb.w, jb.w);
      PK2(zd[0], za.x, za.x); PK2(zd[1], za.y, za.y);
      PK2(zd[2], za.z, za.z); PK2(zd[3], za.w, za.w);
      PK2(zd[4], zb.x, zb.x); PK2(zd[5], zb.y, zb.y);
      PK2(zd[6], zb.z, zb.z); PK2(zd[7], zb.w, zb.w);
      PK2(bp[0], pa.x, pa.y); PK2(bp[1], pa.z, pa.w);
      PK2(bp[2], pb.x, pb.y); PK2(bp[3], pb.z, pb.w);
      float n0 = -ca.x, n1 = -ca.y, n2 = -ca.z, n3 = -ca.w;
      float n4 = -cb.x, n5 = -cb.y, n6 = -cb.z, n7 = -cb.w;
      PK2(zp[0], n0, n1); PK2(zp[1], n2, n3);
      PK2(zp[2], n4, n5); PK2(zp[3], n6, n7);

      #pragma unroll
      for(int ii=0;ii<8;ii++)
        #pragma unroll
        for(int jj=0;jj<4;jj++){
          FMA2(acc[ii][jj], ad[ii], bp[jj]);
          FMA2(acc[ii][jj], zd[ii], zp[jj]);
        }
    }
  }

  __syncthreads();
  float2* rb2 = reinterpret_cast<float2*>(smem);
  #pragma unroll 1
  for(int gg = 0; gg < 4; gg++){
    if(g == gg){
      #pragma unroll
      for(int ii=0;ii<8;ii++){
        int row = ty*8 + ii;
        #pragma unroll
        for(int jj=0;jj<4;jj++){
          float lo, hi;
          UPK2(lo, hi, acc[ii][jj]);
          int idx = row*32 + tx*4 + jj;
          if(gg == 0){
            rb2[idx] = make_float2(lo, hi);
          } else {
            float2 o = rb2[idx];
            o.x += lo; o.y += hi;
            rb2[idx] = o;
          }
        }
      }
    }
    __syncthreads();
  }
  float4* outp = reinterpret_cast<float4*>(
      g_part + ((size_t)b*NPART + blockIdx.x)*DD*DD);
  const float4* rb4 = reinterpret_cast<const float4*>(smem);
  #pragma unroll
  for(int i = 0; i < 4; i++)
    outp[tid + i*256] = rb4[tid + i*256];
}

// Two-stage deterministic reduction of the 148 partials per batch.
__global__ void k_reduce1(){
  int elem = blockIdx.x*256 + threadIdx.x;
  int grp  = blockIdx.y;
  int b    = blockIdx.z;
  const float* base = g_part + (size_t)b*NPART*4096 + elem;
  int s = grp*37;
  float a0=0.f, a1=0.f, a2=0.f, a3=0.f;
  #pragma unroll
  for(int i = 0; i < 36; i += 4){
    a0 += base[(size_t)(s+i  )*4096];
    a1 += base[(size_t)(s+i+1)*4096];
    a2 += base[(size_t)(s+i+2)*4096];
    a3 += base[(size_t)(s+i+3)*4096];
  }
  a0 += base[(size_t)(s+36)*4096];
  g_part2[((b*4 + grp)*4096) + elem] = (a0+a1) + (a2+a3);
}

__global__ void k_reduce2(){
  int elem = blockIdx.x*256 + threadIdx.x;
  int b    = blockIdx.y;
  float v = g_part2[(b*4+0)*4096 + elem]
          + g_part2[(b*4+1)*4096 + elem]
          + g_part2[(b*4+2)*4096 + elem]
          + g_part2[(b*4+3)*4096 + elem];
  g_M[b*4096 + elem] = v;
}

// Householder tridiagonalization, one warp per matrix.
// Row stride 68 floats (4*odd): conflict-free LDS.128 across lanes.
// Householder vector stored at ABSOLUTE column indices with zero-padded
// prefix so all inner loops are 16-aligned float4 with 4 accumulators.
__global__ void k_tridiag(){
  __shared__ __align__(16) float s[64][68];
  __shared__ __align__(16) float vc[64], wc[64];
  __shared__ float ee[64];
  int b = blockIdx.x;
  int lane = threadIdx.x;

  const float* Mb = g_M + b*4096;
  for(int i = lane; i < 4096; i += 32){
    int r = i >> 6, c = i & 63;
    s[r][c] = 0.5f*(Mb[r*64+c] + Mb[c*64+r]);
  }
  __syncwarp();

  // ---- phase 1: k = 0..30 (m >= 33): lane owns rows k+1+lane, k+33+lane ----
  for(int k = 0; k < 31; k++){
    int m = 63 - k;
    int cb = (k + 1) & ~15;
    int nq = (64 - cb) >> 2;                 // float4 count, multiple of 4
    int r0 = k + 1 + lane;
    bool a1 = (lane + 32 < m);
    int r1v = r0 + 32;
    int r1 = a1 ? r1v : 63;
    float x0 = s[r0][k];
    float x1 = a1 ? s[r1v][k] : 0.f;
    float n2 = x0*x0 + x1*x1;
    #pragma unroll
    for(int o = 16; o > 0; o >>= 1) n2 += __shfl_xor_sync(0xffffffffu, n2, o);
    float x00 = __shfl_sync(0xffffffffu, x0, 0);
    float alpha, beta;
    if(n2 < 1e-28f){ alpha = x00; beta = 0.f; }
    else {
      alpha = (x00 >= 0.f) ? -sqrtf(n2) : sqrtf(n2);
      beta  = 1.f/(n2 - alpha*x00);
    }
    if(lane == 0) ee[k] = alpha;
    if(beta != 0.f){
      float v0 = (lane == 0) ? (x00 - alpha) : x0;
      float v1 = a1 ? x1 : 0.f;
      int c0 = cb + lane;
      if(c0 <= k) vc[c0] = 0.f;
      vc[k+1+lane] = v0;
      int c2 = k + 33 + lane;
      if(c2 < 64) vc[c2] = v1;
      __syncwarp();

      const float4* row04 = reinterpret_cast<const float4*>(&s[r0][0]);
      const float4* row14 = reinterpret_cast<const float4*>(&s[r1][0]);
      const float4* vc4   = reinterpret_cast<const float4*>(vc);
      float pA=0.f, pB=0.f, pC=0.f, pD=0.f;
      float qA=0.f, qB=0.f, qC=0.f, qD=0.f;
      int q0 = cb >> 2;
      #pragma unroll 4
      for(int q = 0; q < nq; q += 4){
        float4 vA = vc4[q0+q],   vB = vc4[q0+q+1], vC = vc4[q0+q+2], vD = vc4[q0+q+3];
        float4 rA = row04[q0+q], rB = row04[q0+q+1], rC = row04[q0+q+2], rD = row04[q0+q+3];
        float4 sA = row14[q0+q], sB = row14[q0+q+1], sC = row14[q0+q+2], sD = row14[q0+q+3];
        pA = fmaf(rA.x,vA.x,fmaf(rA.y,vA.y,fmaf(rA.z,vA.z,fmaf(rA.w,vA.w,pA))));
        pB = fmaf(rB.x,vB.x,fmaf(rB.y,vB.y,fmaf(rB.z,vB.z,fmaf(rB.w,vB.w,pB))));
        pC = fmaf(rC.x,vC.x,fmaf(rC.y,vC.y,fmaf(rC.z,vC.z,fmaf(rC.w,vC.w,pC))));
        pD = fmaf(rD.x,vD.x,fmaf(rD.y,vD.y,fmaf(rD.z,vD.z,fmaf(rD.w,vD.w,pD))));
        qA = fmaf(sA.x,vA.x,fmaf(sA.y,vA.y,fmaf(sA.z,vA.z,fmaf(sA.w,vA.w,qA))));
        qB = fmaf(sB.x,vB.x,fmaf(sB.y,vB.y,fmaf(sB.z,vB.z,fmaf(sB.w,vB.w,qB))));
        qC = fmaf(sC.x,vC.x,fmaf(sC.y,vC.y,fmaf(sC.z,vC.z,fmaf(sC.w,vC.w,qC))));
        qD = fmaf(sD.x,vD.x,fmaf(sD.y,vD.y,fmaf(sD.z,vD.z,fmaf(sD.w,vD.w,qD))));
      }
      float p0 = beta*((pA+pB) + (pC+pD));
      float p1 = beta*((qA+qB) + (qC+qD));
      float ptv = p0*v0 + p1*v1;
      #pragma unroll
      for(int o = 16; o > 0; o >>= 1) ptv += __shfl_xor_sync(0xffffffffu, ptv, o);
      float K = 0.5f*beta*ptv;
      float w0 = p0 - K*v0;
      float w1 = a1 ? (p1 - K*v1) : 0.f;
      if(c0 <= k) wc[c0] = 0.f;
      wc[k+1+lane] = w0;
      if(c2 < 64) wc[c2] = w1;
      __syncwarp();

      float4* u04 = reinterpret_cast<float4*>(&s[r0][0]);
      const float4* wc4 = reinterpret_cast<const float4*>(wc);
      #pragma unroll 4
      for(int q = q0; q < q0 + nq; q++){
        float4 vq = vc4[q], wq = wc4[q];
        float4 r = u04[q];
        r.x -= v0*wq.x + w0*vq.x;
        r.y -= v0*wq.y + w0*vq.y;
        r.z -= v0*wq.z + w0*vq.z;
        r.w -= v0*wq.w + w0*vq.w;
        u04[q] = r;
      }
      if(a1){
        float4* u14 = reinterpret_cast<float4*>(&s[r1v][0]);
        #pragma unroll 4
        for(int q = q0; q < q0 + nq; q++){
          float4 vq = vc4[q], wq = wc4[q];
          float4 r = u14[q];
          r.x -= v1*wq.x + w1*vq.x;
          r.y -= v1*wq.y + w1*vq.y;
          r.z -= v1*wq.z + w1*vq.z;
          r.w -= v1*wq.w + w1*vq.w;
          u14[q] = r;
        }
      }
      __syncwarp();
    }
  }

  // ---- phase 2: k = 31..61 (m <= 32): lane owns at most one row ----
  for(int k = 31; k < 62; k++){
    int m = 63 - k;
    int cb = (k + 1) & ~15;
    int nq = (64 - cb) >> 2;
    bool a0 = (lane < m);
    int r0v = k + 1 + lane;
    int r0 = a0 ? r0v : 63;
    float x0 = a0 ? s[r0v][k] : 0.f;
    float n2 = x0*x0;
    #pragma unroll
    for(int o = 16; o > 0; o >>= 1) n2 += __shfl_xor_sync(0xffffffffu, n2, o);
    float x00 = __shfl_sync(0xffffffffu, x0, 0);
    float alpha, beta;
    if(n2 < 1e-28f){ alpha = x00; beta = 0.f; }
    else {
      alpha = (x00 >= 0.f) ? -sqrtf(n2) : sqrtf(n2);
      beta  = 1.f/(n2 - alpha*x00);
    }
    if(lane == 0) ee[k] = alpha;
    if(beta != 0.f){
      float v0 = a0 ? ((lane == 0) ? (x00 - alpha) : x0) : 0.f;
      int c0 = cb + lane;
      if(c0 <= k) vc[c0] = 0.f;
      int c1 = k + 1 + lane;
      if(c1 < 64) vc[c1] = v0;
      __syncwarp();

      const float4* row04 = reinterpret_cast<const float4*>(&s[r0][0]);
      const float4* vc4   = reinterpret_cast<const float4*>(vc);
      float pA=0.f, pB=0.f, pC=0.f, pD=0.f;
      int q0 = cb >> 2;
      #pragma unroll 4
      for(int q = 0; q < nq; q += 4){
        float4 vA = vc4[q0+q],   vB = vc4[q0+q+1], vC = vc4[q0+q+2], vD = vc4[q0+q+3];
        float4 rA = row04[q0+q], rB = row04[q0+q+1], rC = row04[q0+q+2], rD = row04[q0+q+3];
        pA = fmaf(rA.x,vA.x,fmaf(rA.y,vA.y,fmaf(rA.z,vA.z,fmaf(rA.w,vA.w,pA))));
        pB = fmaf(rB.x,vB.x,fmaf(rB.y,vB.y,fmaf(rB.z,vB.z,fmaf(rB.w,vB.w,pB))));
        pC = fmaf(rC.x,vC.x,fmaf(rC.y,vC.y,fmaf(rC.z,vC.z,fmaf(rC.w,vC.w,pC))));
        pD = fmaf(rD.x,vD.x,fmaf(rD.y,vD.y,fmaf(rD.z,vD.z,fmaf(rD.w,vD.w,pD))));
      }
      float p0 = beta*((pA+pB) + (pC+pD));
      float ptv = p0*v0;
      #pragma unroll
      for(int o = 16; o > 0; o >>= 1) ptv += __shfl_xor_sync(0xffffffffu, ptv, o);
      float K = 0.5f*beta*ptv;
      float w0 = a0 ? (p0 - K*v0) : 0.f;
      if(c0 <= k) wc[c0] = 0.f;
      if(c1 < 64) wc[c1] = w0;
      __syncwarp();

      if(a0){
        float4* u04 = reinterpret_cast<float4*>(&s[r0v][0]);
        const float4* wc4 = reinterpret_cast<const float4*>(wc);
        #pragma unroll 4
        for(int q = q0; q < q0 + nq; q++){
          float4 vq = vc4[q], wq = wc4[q];
          float4 r = u04[q];
          r.x -= v0*wq.x + w0*vq.x;
          r.y -= v0*wq.y + w0*vq.y;
          r.z -= v0*wq.z + w0*vq.z;
          r.w -= v0*wq.w + w0*vq.w;
          u04[q] = r;
        }
      }
      __syncwarp();
    }
  }

  if(lane == 0) ee[62] = s[63][62];
  __syncwarp();
  g_td[b*128 + lane]      = s[lane][lane];
  g_td[b*128 + lane + 32] = s[lane+32][lane+32];
  if(lane < 31) g_td[b*128 + 64 + lane] = ee[lane];
  g_td[b*128 + 64 + 31 + lane] = ee[31 + lane];
}

// 4-way multisection (4 probes per eigenvalue, interval shrinks 5x/round).
__global__ void k_bisect(){
  __shared__ float d[64], e2s[64];
  __shared__ float loA[64], hiA[64];
  __shared__ float bnd[2];
  __shared__ float red[64];
  int b = blockIdx.x;
  int tid = threadIdx.x;
  if(tid < 64) d[tid] = g_td[b*128 + tid];
  if(tid < 63){ float e = g_td[b*128 + 64 + tid]; e2s[tid] = e*e; }
  __syncthreads();
  if(tid < 64){
    float el = (tid > 0)  ? sqrtf(e2s[tid-1]) : 0.f;
    float er = (tid < 63) ? sqrtf(e2s[tid])   : 0.f;
    loA[tid] = d[tid] - el - er;
    hiA[tid] = d[tid] + el + er;
  }
  __syncthreads();
  if(tid < 32){
    float lo = fminf(loA[tid], loA[tid+32]);
    float hi = fmaxf(hiA[tid], hiA[tid+32]);
    #pragma unroll
    for(int o = 16; o > 0; o >>= 1){
      lo = fminf(lo, __shfl_down_sync(0xffffffffu, lo, o));
      hi = fmaxf(hi, __shfl_down_sync(0xffffffffu, hi, o));
    }
    if(tid == 0){ bnd[0] = lo; bnd[1] = hi; }
  }
  __syncthreads();

  int j = tid >> 2;
  int t = tid & 3;
  int wl = tid & 31;
  unsigned base = wl & ~3u;
  float lo = bnd[0], hi = bnd[1];

  #pragma unroll 1
  for(int r = 0; r < 10; r++){
    float mid = lo + (hi - lo)*0.2f*(float)(t+1);
    int cnt = 0;
    float q = d[0] - mid;
    cnt += (q < 0.f);
    #pragma unroll 1
    for(int i = 1; i < 64; i++){
      float aq = fabsf(q);
      float denom = (aq < 1e-25f) ? ((q < 0.f) ? -1e-25f : 1e-25f) : q;
      q = (d[i] - mid) - __fdividef(e2s[i-1], denom);
      cnt += (q < 0.f);
    }
    int less = (cnt > j);
    #pragma unroll
    for(int s2 = 0; s2 < 4; s2++){
      float ms = __shfl_sync(0xffffffffu, mid,  base + s2);
      int   ls = __shfl_sync(0xffffffffu, less, base + s2);
      if(ls) hi = fminf(hi, ms); else lo = fmaxf(lo, ms);
    }
  }

  float lam = 0.5f*(lo + hi);
  float val = (t == 0 && lam > 0.f) ? sqrtf(lam) : 0.f;
  #pragma unroll
  for(int o = 16; o > 0; o >>= 1) val += __shfl_down_sync(0xffffffffu, val, o);
  if(wl == 0) red[tid >> 5] = val;
  __syncthreads();
  if(tid == 0){
    float sum = 0.f;
    #pragma unroll
    for(int w = 0; w < 8; w++) sum += red[w];
    g_trace[b] = sum;
  }
}

__global__ void k_final(float* out){
  if(threadIdx.x == 0)
    out[0] = 0.25f*(g_trace[0] + g_trace[1] + g_trace[2] + g_trace[3]);
}

extern "C" void kernel_launch(void* const* d_in, const int* in_sizes, int n_in,
                              void* d_out, int out_size){
  const float* x  = (const float*)d_in[0];
  const float* J  = (const float*)d_in[1];
  const int*   e0 = (const int*)d_in[2];
  const int*   e1 = (const int*)d_in[3];
  int E = in_sizes[2];
  float* out = (float*)d_out;

  k_rowptr<<<(E + 255)/256, 256>>>(e0, E);
  k_phaseA<<<(2*NN)/8, 256>>>(x, J, e1, 0);
  k_phaseA<<<(2*NN)/8, 256>>>(x, J, e1, 2);
  k_gram<<<dim3(SPLIT, BB), 256>>>(J);
  k_reduce1<<<dim3(16, 4, BB), 256>>>();
  k_reduce2<<<dim3(16, BB), 256>>>();
  k_tridiag<<<BB, 32>>>();
  k_bisect<<<BB, 256>>>();
  k_final<<<1, 32>>>(out);
}

// round 7
// speedup vs baseline: 1.9034x; 1.2384x over previous
#include <cuda_runtime.h>
#include <math.h>
#include <stdint.h>

#define BB 4
#define NN 25600
#define DD 64
#define RR (3*NN)
#define SPLIT 148
#define NPART SPLIT
#define KT 32
#define SS 72   // smem row stride (floats): (8t+g)%32 distinct -> conflict-free frags

typedef unsigned long long ull;

__device__ float g_P[(size_t)BB*RR*DD];
__device__ float g_Z[(size_t)BB*RR*DD];
__device__ float g_part[(size_t)BB*NPART*DD*DD];
__device__ float g_part2[BB*4*DD*DD];
__device__ float g_M[BB*DD*DD];
__device__ float g_td[BB*128];     // per batch: d[64], e[63]
__device__ float g_trace[BB];
__device__ int   g_rowptr[NN+1];

__device__ __forceinline__ float totf32(float x){
  uint32_t r; asm("cvt.rna.tf32.f32 %0, %1;" : "=r"(r) : "f"(x));
  return __uint_as_float(r);
}

#define MMA_TF32(c, a0,a1,a2,a3, b0,b1) \
  asm("mma.sync.aligned.m16n8k8.row.col.f32.tf32.tf32.f32 " \
      "{%0,%1,%2,%3}, {%4,%5,%6,%7}, {%8,%9}, {%0,%1,%2,%3};" \
      : "+f"(c[0]),"+f"(c[1]),"+f"(c[2]),"+f"(c[3]) \
      : "r"(a0),"r"(a1),"r"(a2),"r"(a3), "r"(b0),"r"(b1))

// Build CSR row pointers from the lexicographically sorted e0 array.
__global__ void k_rowptr(const int* __restrict__ e0, int E){
  int i = blockIdx.x*blockDim.x + threadIdx.x;
  if(i >= E) return;
  int cur  = e0[i];
  int prev = (i==0) ? -1 : e0[i-1];
  for(int n = prev+1; n <= cur; n++) g_rowptr[n] = i;
  if(i == E-1){
    for(int n = cur+1; n <= NN; n++) g_rowptr[n] = E;
  }
}

// One warp per (batch, node): P = LJ rows, Z = Lc^{-1} BTJ rows.
__global__ void k_phaseA(const float* __restrict__ x, const float* __restrict__ J,
                         const int* __restrict__ e1, int boff)
{
  int gw   = (blockIdx.x*blockDim.x + threadIdx.x) >> 5;
  int lane = threadIdx.x & 31;
  if(gw >= 2*NN) return;
  int b = boff + gw / NN;
  int n = gw % NN;

  const float* xb = x + (size_t)b*NN*3;
  const float* Jb = J + (size_t)b*RR*DD;
  int rs = g_rowptr[n], re = g_rowptr[n+1];
  float deg = (float)(re - rs);
  float xn0 = xb[3*n], xn1 = xb[3*n+1], xn2 = xb[3*n+2];

  float g10x=0,g10y=0,g11x=0,g11y=0,g12x=0,g12y=0;
  float g20x=0,g20y=0,g21x=0,g21y=0,g22x=0,g22y=0;
  float c00=0,c11=0,c22=0,c01=0,c02=0,c12=0;
  float vs0=0,vs1=0,vs2=0;

  for(int e = rs; e < re; e++){
    int m = e1[e];
    float v0 = xn0 - xb[3*m];
    float v1 = xn1 - xb[3*m+1];
    float v2 = xn2 - xb[3*m+2];
    const float2* Jm = reinterpret_cast<const float2*>(Jb + (size_t)m*192);
    float2 j0 = Jm[lane];
    float2 j1 = Jm[32+lane];
    float2 j2 = Jm[64+lane];
    g10x += j0.x; g10y += j0.y;
    g11x += j1.x; g11y += j1.y;
    g12x += j2.x; g12y += j2.y;
    g20x += v1*j2.x - v2*j1.x;  g20y += v1*j2.y - v2*j1.y;
    g21x += v2*j0.x - v0*j2.x;  g21y += v2*j0.y - v0*j2.y;
    g22x += v0*j1.x - v1*j0.x;  g22y += v0*j1.y - v1*j0.y;
    float vv = v0*v0 + v1*v1 + v2*v2;
    c00 += vv - v0*v0;
    c11 += vv - v1*v1;
    c22 += vv - v2*v2;
    c01 -= v0*v1; c02 -= v0*v2; c12 -= v1*v2;
    vs0 += v0; vs1 += v1; vs2 += v2;
  }

  const float2* Jn = reinterpret_cast<const float2*>(Jb + (size_t)n*192);
  float2 a0 = Jn[lane], a1 = Jn[32+lane], a2 = Jn[64+lane];

  float2* Pp = reinterpret_cast<float2*>(g_P + ((size_t)b*NN + n)*192);
  float2 p0, p1, p2;
  p0.x = 2.f*(deg*a0.x - g10x); p0.y = 2.f*(deg*a0.y - g10y);
  p1.x = 2.f*(deg*a1.x - g11x); p1.y = 2.f*(deg*a1.y - g11y);
  p2.x = 2.f*(deg*a2.x - g12x); p2.y = 2.f*(deg*a2.y - g12y);
  Pp[lane] = p0; Pp[32+lane] = p1; Pp[64+lane] = p2;

  float q0x = g20x - (vs1*a2.x - vs2*a1.x);
  float q0y = g20y - (vs1*a2.y - vs2*a1.y);
  float q1x = g21x - (vs2*a0.x - vs0*a2.x);
  float q1y = g21y - (vs2*a0.y - vs0*a2.y);
  float q2x = g22x - (vs0*a1.x - vs1*a0.x);
  float q2y = g22y - (vs0*a1.y - vs1*a0.y);

  float l00 = sqrtf(fmaxf(c00, 1e-30f));
  float i00 = 1.f/l00;
  float l10 = c01*i00, l20 = c02*i00;
  float l11 = sqrtf(fmaxf(c11 - l10*l10, 1e-30f));
  float i11 = 1.f/l11;
  float l21 = (c12 - l20*l10)*i11;
  float l22 = sqrtf(fmaxf(c22 - l20*l20 - l21*l21, 1e-30f));
  float i22 = 1.f/l22;

  float2 z0, z1, z2;
  z0.x = q0x*i00;                           z0.y = q0y*i00;
  z1.x = (q1x - l10*z0.x)*i11;              z1.y = (q1y - l10*z0.y)*i11;
  z2.x = (q2x - l20*z0.x - l21*z1.x)*i22;   z2.y = (q2y - l20*z0.y - l21*z1.y)*i22;

  float2* Zp = reinterpret_cast<float2*>(g_Z + ((size_t)b*NN + n)*192);
  Zp[lane] = z0; Zp[32+lane] = z1; Zp[64+lane] = z2;
}

// M_partial = J^T P - Z^T Z via tf32 tensor-core mma (m16n8k8).
// 8 warps: warp w owns C rows [16*(w>>1),+16) x cols [32*(w&1),+32).
__global__ void __launch_bounds__(256) k_gram(const float* __restrict__ J){
  __shared__ __align__(16) float sJ[KT*SS];
  __shared__ __align__(16) float sP[KT*SS];
  __shared__ __align__(16) float sZ[KT*SS];
  int b    = blockIdx.y;
  int tid  = threadIdx.x;
  int w    = tid >> 5;
  int lane = tid & 31;
  int g    = lane >> 2;      // group id 0..7
  int t    = lane & 3;       // thread-in-group 0..3
  int ib   = (w >> 1) * 16;  // C row base
  int jb   = (w & 1) * 32;   // C col base

  const float4* gJ = reinterpret_cast<const float4*>(J   + (size_t)b*RR*DD);
  const float4* gP = reinterpret_cast<const float4*>(g_P + (size_t)b*RR*DD);
  const float4* gZ = reinterpret_cast<const float4*>(g_Z + (size_t)b*RR*DD);

  float accJ[4][4], accZ[4][4];
  #pragma unroll
  for(int s=0;s<4;s++)
    #pragma unroll
    for(int r=0;r<4;r++){ accJ[s][r]=0.f; accZ[s][r]=0.f; }

  const int ntiles = RR/KT;   // 2400
  for(int tt = blockIdx.x; tt < ntiles; tt += SPLIT){
    size_t base4 = (size_t)tt*512;
    __syncthreads();
    #pragma unroll
    for(int i=0;i<2;i++){
      int idx = tid + i*256;        // 0..511
      int k   = idx >> 4;
      int c4  = idx & 15;
      int so  = k*SS + c4*4;
      float4 vj = gJ[base4+idx];
      float4 vp = gP[base4+idx];
      float4 vz = gZ[base4+idx];
      vj.x=totf32(vj.x); vj.y=totf32(vj.y); vj.z=totf32(vj.z); vj.w=totf32(vj.w);
      vp.x=totf32(vp.x); vp.y=totf32(vp.y); vp.z=totf32(vp.z); vp.w=totf32(vp.w);
      vz.x=totf32(vz.x); vz.y=totf32(vz.y); vz.z=totf32(vz.z); vz.w=totf32(vz.w);
      *reinterpret_cast<float4*>(sJ + so) = vj;
      *reinterpret_cast<float4*>(sP + so) = vp;
      *reinterpret_cast<float4*>(sZ + so) = vz;
    }
    __syncthreads();
    #pragma unroll
    for(int k8 = 0; k8 < 4; k8++){
      int kb = k8*8;
      // A fragments (A[i][k] = s*[kb+k][ib+i])
      int rlo = (kb+t)*SS, rhi = (kb+t+4)*SS;
      uint32_t aj0 = __float_as_uint(sJ[rlo + ib + g]);
      uint32_t aj1 = __float_as_uint(sJ[rlo + ib + g + 8]);
      uint32_t aj2 = __float_as_uint(sJ[rhi + ib + g]);
      uint32_t aj3 = __float_as_uint(sJ[rhi + ib + g + 8]);
      uint32_t az0 = __float_as_uint(sZ[rlo + ib + g]);
      uint32_t az1 = __float_as_uint(sZ[rlo + ib + g + 8]);
      uint32_t az2 = __float_as_uint(sZ[rhi + ib + g]);
      uint32_t az3 = __float_as_uint(sZ[rhi + ib + g + 8]);
      #pragma unroll
      for(int s = 0; s < 4; s++){
        int j0 = jb + s*8;
        uint32_t bp0 = __float_as_uint(sP[rlo + j0 + g]);
        uint32_t bp1 = __float_as_uint(sP[rhi + j0 + g]);
        uint32_t bz0 = __float_as_uint(sZ[rlo + j0 + g]);
        uint32_t bz1 = __float_as_uint(sZ[rhi + j0 + g]);
        MMA_TF32(accJ[s], aj0,aj1,aj2,aj3, bp0,bp1);
        MMA_TF32(accZ[s], az0,az1,az2,az3, bz0,bz1);
      }
    }
  }

  float* outp = g_part + ((size_t)b*NPART + blockIdx.x)*DD*DD;
  int row = ib + g;
  #pragma unroll
  for(int s = 0; s < 4; s++){
    int col = jb + s*8 + 2*t;
    outp[row*64 + col]       = accJ[s][0] - accZ[s][0];
    outp[row*64 + col + 1]   = accJ[s][1] - accZ[s][1];
    outp[(row+8)*64 + col]   = accJ[s][2] - accZ[s][2];
    outp[(row+8)*64 + col+1] = accJ[s][3] - accZ[s][3];
  }
}

// Two-stage deterministic reduction of the 148 partials per batch.
__global__ void k_reduce1(){
  int elem = blockIdx.x*256 + threadIdx.x;
  int grp  = blockIdx.y;
  int b    = blockIdx.z;
  const float* base = g_part + (size_t)b*NPART*4096 + elem;
  int s = grp*37;
  float a0=0.f, a1=0.f, a2=0.f, a3=0.f;
  #pragma unroll
  for(int i = 0; i < 36; i += 4){
    a0 += base[(size_t)(s+i  )*4096];
    a1 += base[(size_t)(s+i+1)*4096];
    a2 += base[(size_t)(s+i+2)*4096];
    a3 += base[(size_t)(s+i+3)*4096];
  }
  a0 += base[(size_t)(s+36)*4096];
  g_part2[((b*4 + grp)*4096) + elem] = (a0+a1) + (a2+a3);
}

__global__ void k_reduce2(){
  int elem = blockIdx.x*256 + threadIdx.x;
  int b    = blockIdx.y;
  float v = g_part2[(b*4+0)*4096 + elem]
          + g_part2[(b*4+1)*4096 + elem]
          + g_part2[(b*4+2)*4096 + elem]
          + g_part2[(b*4+3)*4096 + elem];
  g_M[b*4096 + elem] = v;
}

// Householder tridiagonalization, one warp per matrix (float4 inner loops).
__global__ void k_tridiag(){
  __shared__ __align__(16) float s[64][68];
  __shared__ __align__(16) float vc[64], wc[64];
  __shared__ float ee[64];
  int b = blockIdx.x;
  int lane = threadIdx.x;

  const float* Mb = g_M + b*4096;
  for(int i = lane; i < 4096; i += 32){
    int r = i >> 6, c = i & 63;
    s[r][c] = 0.5f*(Mb[r*64+c] + Mb[c*64+r]);
  }
  __syncwarp();

  for(int k = 0; k < 31; k++){
    int m = 63 - k;
    int cb = (k + 1) & ~15;
    int nq = (64 - cb) >> 2;
    int r0 = k + 1 + lane;
    bool a1 = (lane + 32 < m);
    int r1v = r0 + 32;
    int r1 = a1 ? r1v : 63;
    float x0 = s[r0][k];
    float x1 = a1 ? s[r1v][k] : 0.f;
    float n2 = x0*x0 + x1*x1;
    #pragma unroll
    for(int o = 16; o > 0; o >>= 1) n2 += __shfl_xor_sync(0xffffffffu, n2, o);
    float x00 = __shfl_sync(0xffffffffu, x0, 0);
    float alpha, beta;
    if(n2 < 1e-28f){ alpha = x00; beta = 0.f; }
    else {
      alpha = (x00 >= 0.f) ? -sqrtf(n2) : sqrtf(n2);
      beta  = 1.f/(n2 - alpha*x00);
    }
    if(lane == 0) ee[k] = alpha;
    if(beta != 0.f){
      float v0 = (lane == 0) ? (x00 - alpha) : x0;
      float v1 = a1 ? x1 : 0.f;
      int c0 = cb + lane;
      if(c0 <= k) vc[c0] = 0.f;
      vc[k+1+lane] = v0;
      int c2 = k + 33 + lane;
      if(c2 < 64) vc[c2] = v1;
      __syncwarp();

      const float4* row04 = reinterpret_cast<const float4*>(&s[r0][0]);
      const float4* row14 = reinterpret_cast<const float4*>(&s[r1][0]);
      const float4* vc4   = reinterpret_cast<const float4*>(vc);
      float pA=0.f, pB=0.f, pC=0.f, pD=0.f;
      float qA=0.f, qB=0.f, qC=0.f, qD=0.f;
      int q0 = cb >> 2;
      #pragma unroll 4
      for(int q = 0; q < nq; q += 4){
        float4 vA = vc4[q0+q],   vB = vc4[q0+q+1], vC = vc4[q0+q+2], vD = vc4[q0+q+3];
        float4 rA = row04[q0+q], rB = row04[q0+q+1], rC = row04[q0+q+2], rD = row04[q0+q+3];
        float4 sA = row14[q0+q], sB = row14[q0+q+1], sC = row14[q0+q+2], sD = row14[q0+q+3];
        pA = fmaf(rA.x,vA.x,fmaf(rA.y,vA.y,fmaf(rA.z,vA.z,fmaf(rA.w,vA.w,pA))));
        pB = fmaf(rB.x,vB.x,fmaf(rB.y,vB.y,fmaf(rB.z,vB.z,fmaf(rB.w,vB.w,pB))));
        pC = fmaf(rC.x,vC.x,fmaf(rC.y,vC.y,fmaf(rC.z,vC.z,fmaf(rC.w,vC.w,pC))));
        pD = fmaf(rD.x,vD.x,fmaf(rD.y,vD.y,fmaf(rD.z,vD.z,fmaf(rD.w,vD.w,pD))));
        qA = fmaf(sA.x,vA.x,fmaf(sA.y,vA.y,fmaf(sA.z,vA.z,fmaf(sA.w,vA.w,qA))));
        qB = fmaf(sB.x,vB.x,fmaf(sB.y,vB.y,fmaf(sB.z,vB.z,fmaf(sB.w,vB.w,qB))));
        qC = fmaf(sC.x,vC.x,fmaf(sC.y,vC.y,fmaf(sC.z,vC.z,fmaf(sC.w,vC.w,qC))));
        qD = fmaf(sD.x,vD.x,fmaf(sD.y,vD.y,fmaf(sD.z,vD.z,fmaf(sD.w,vD.w,qD))));
      }
      float p0 = beta*((pA+pB) + (pC+pD));
      float p1 = beta*((qA+qB) + (qC+qD));
      float ptv = p0*v0 + p1*v1;
      #pragma unroll
      for(int o = 16; o > 0; o >>= 1) ptv += __shfl_xor_sync(0xffffffffu, ptv, o);
      float K = 0.5f*beta*ptv;
      float w0 = p0 - K*v0;
      float w1 = a1 ? (p1 - K*v1) : 0.f;
      if(c0 <= k) wc[c0] = 0.f;
      wc[k+1+lane] = w0;
      if(c2 < 64) wc[c2] = w1;
      __syncwarp();

      float4* u04 = reinterpret_cast<float4*>(&s[r0][0]);
      const float4* wc4 = reinterpret_cast<const float4*>(wc);
      #pragma unroll 4
      for(int q = q0; q < q0 + nq; q++){
        float4 vq = vc4[q], wq = wc4[q];
        float4 r = u04[q];
        r.x -= v0*wq.x + w0*vq.x;
        r.y -= v0*wq.y + w0*vq.y;
        r.z -= v0*wq.z + w0*vq.z;
        r.w -= v0*wq.w + w0*vq.w;
        u04[q] = r;
      }
      if(a1){
        float4* u14 = reinterpret_cast<float4*>(&s[r1v][0]);
        #pragma unroll 4
        for(int q = q0; q < q0 + nq; q++){
          float4 vq = vc4[q], wq = wc4[q];
          float4 r = u14[q];
          r.x -= v1*wq.x + w1*vq.x;
          r.y -= v1*wq.y + w1*vq.y;
          r.z -= v1*wq.z + w1*vq.z;
          r.w -= v1*wq.w + w1*vq.w;
          u14[q] = r;
        }
      }
      __syncwarp();
    }
  }

  for(int k = 31; k < 62; k++){
    int m = 63 - k;
    int cb = (k + 1) & ~15;
    int nq = (64 - cb) >> 2;
    bool a0 = (lane < m);
    int r0v = k + 1 + lane;
    int r0 = a0 ? r0v : 63;
    float x0 = a0 ? s[r0v][k] : 0.f;
    float n2 = x0*x0;
    #pragma unroll
    for(int o = 16; o > 0; o >>= 1) n2 += __shfl_xor_sync(0xffffffffu, n2, o);
    float x00 = __shfl_sync(0xffffffffu, x0, 0);
    float alpha, beta;
    if(n2 < 1e-28f){ alpha = x00; beta = 0.f; }
    else {
      alpha = (x00 >= 0.f) ? -sqrtf(n2) : sqrtf(n2);
      beta  = 1.f/(n2 - alpha*x00);
    }
    if(lane == 0) ee[k] = alpha;
    if(beta != 0.f){
      float v0 = a0 ? ((lane == 0) ? (x00 - alpha) : x0) : 0.f;
      int c0 = cb + lane;
      if(c0 <= k) vc[c0] = 0.f;
      int c1 = k + 1 + lane;
      if(c1 < 64) vc[c1] = v0;
      __syncwarp();

      const float4* row04 = reinterpret_cast<const float4*>(&s[r0][0]);
      const float4* vc4   = reinterpret_cast<const float4*>(vc);
      float pA=0.f, pB=0.f, pC=0.f, pD=0.f;
      int q0 = cb >> 2;
      #pragma unroll 4
      for(int q = 0; q < nq; q += 4){
        float4 vA = vc4[q0+q],   vB = vc4[q0+q+1], vC = vc4[q0+q+2], vD = vc4[q0+q+3];
        float4 rA = row04[q0+q], rB = row04[q0+q+1], rC = row04[q0+q+2], rD = row04[q0+q+3];
        pA = fmaf(rA.x,vA.x,fmaf(rA.y,vA.y,fmaf(rA.z,vA.z,fmaf(rA.w,vA.w,pA))));
        pB = fmaf(rB.x,vB.x,fmaf(rB.y,vB.y,fmaf(rB.z,vB.z,fmaf(rB.w,vB.w,pB))));
        pC = fmaf(rC.x,vC.x,fmaf(rC.y,vC.y,fmaf(rC.z,vC.z,fmaf(rC.w,vC.w,pC))));
        pD = fmaf(rD.x,vD.x,fmaf(rD.y,vD.y,fmaf(rD.z,vD.z,fmaf(rD.w,vD.w,pD))));
      }
      float p0 = beta*((pA+pB) + (pC+pD));
      float ptv = p0*v0;
      #pragma unroll
      for(int o = 16; o > 0; o >>= 1) ptv += __shfl_xor_sync(0xffffffffu, ptv, o);
      float K = 0.5f*beta*ptv;
      float w0 = a0 ? (p0 - K*v0) : 0.f;
      if(c0 <= k) wc[c0] = 0.f;
      if(c1 < 64) wc[c1] = w0;
      __syncwarp();

      if(a0){
        float4* u04 = reinterpret_cast<float4*>(&s[r0v][0]);
        const float4* wc4 = reinterpret_cast<const float4*>(wc);
        #pragma unroll 4
        for(int q = q0; q < q0 + nq; q++){
          float4 vq = vc4[q], wq = wc4[q];
          float4 r = u04[q];
          r.x -= v0*wq.x + w0*vq.x;
          r.y -= v0*wq.y + w0*vq.y;
          r.z -= v0*wq.z + w0*vq.z;
          r.w -= v0*wq.w + w0*vq.w;
          u04[q] = r;
        }
      }
      __syncwarp();
    }
  }

  if(lane == 0) ee[62] = s[63][62];
  __syncwarp();
  g_td[b*128 + lane]      = s[lane][lane];
  g_td[b*128 + lane + 32] = s[lane+32][lane+32];
  if(lane < 31) g_td[b*128 + 64 + lane] = ee[lane];
  g_td[b*128 + 64 + 31 + lane] = ee[31 + lane];
}

// 4-way multisection (4 probes per eigenvalue, interval shrinks 5x/round).
__global__ void k_bisect(){
  __shared__ float d[64], e2s[64];
  __shared__ float loA[64], hiA[64];
  __shared__ float bnd[2];
  __shared__ float red[64];
  int b = blockIdx.x;
  int tid = threadIdx.x;
  if(tid < 64) d[tid] = g_td[b*128 + tid];
  if(tid < 63){ float e = g_td[b*128 + 64 + tid]; e2s[tid] = e*e; }
  __syncthreads();
  if(tid < 64){
    float el = (tid > 0)  ? sqrtf(e2s[tid-1]) : 0.f;
    float er = (tid < 63) ? sqrtf(e2s[tid])   : 0.f;
    loA[tid] = d[tid] - el - er;
    hiA[tid] = d[tid] + el + er;
  }
  __syncthreads();
  if(tid < 32){
    float lo = fminf(loA[tid], loA[tid+32]);
    float hi = fmaxf(hiA[tid], hiA[tid+32]);
    #pragma unroll
    for(int o = 16; o > 0; o >>= 1){
      lo = fminf(lo, __shfl_down_sync(0xffffffffu, lo, o));
      hi = fmaxf(hi, __shfl_down_sync(0xffffffffu, hi, o));
    }
    if(tid == 0){ bnd[0] = lo; bnd[1] = hi; }
  }
  __syncthreads();

  int j = tid >> 2;
  int t = tid & 3;
  int wl = tid & 31;
  unsigned base = wl & ~3u;
  float lo = bnd[0], hi = bnd[1];

  #pragma unroll 1
  for(int r = 0; r < 10; r++){
    float mid = lo + (hi - lo)*0.2f*(float)(t+1);
    int cnt = 0;
    float q = d[0] - mid;
    cnt += (q < 0.f);
    #pragma unroll 1
    for(int i = 1; i < 64; i++){
      float aq = fabsf(q);
      float denom = (aq < 1e-25f) ? ((q < 0.f) ? -1e-25f : 1e-25f) : q;
      q = (d[i] - mid) - __fdividef(e2s[i-1], denom);
      cnt += (q < 0.f);
    }
    int less = (cnt > j);
    #pragma unroll
    for(int s2 = 0; s2 < 4; s2++){
      float ms = __shfl_sync(0xffffffffu, mid,  base + s2);
      int   ls = __shfl_sync(0xffffffffu, less, base + s2);
      if(ls) hi = fminf(hi, ms); else lo = fmaxf(lo, ms);
    }
  }

  float lam = 0.5f*(lo + hi);
  float val = (t == 0 && lam > 0.f) ? sqrtf(lam) : 0.f;
  #pragma unroll
  for(int o = 16; o > 0; o >>= 1) val += __shfl_down_sync(0xffffffffu, val, o);
  if(wl == 0) red[tid >> 5] = val;
  __syncthreads();
  if(tid == 0){
    float sum = 0.f;
    #pragma unroll
    for(int w = 0; w < 8; w++) sum += red[w];
    g_trace[b] = sum;
  }
}

__global__ void k_final(float* out){
  if(threadIdx.x == 0)
    out[0] = 0.25f*(g_trace[0] + g_trace[1] + g_trace[2] + g_trace[3]);
}

extern "C" void kernel_launch(void* const* d_in, const int* in_sizes, int n_in,
                              void* d_out, int out_size){
  const float* x  = (const float*)d_in[0];
  const float* J  = (const float*)d_in[1];
  const int*   e0 = (const int*)d_in[2];
  const int*   e1 = (const int*)d_in[3];
  int E = in_sizes[2];
  float* out = (float*)d_out;

  k_rowptr<<<(E + 255)/256, 256>>>(e0, E);
  k_phaseA<<<(2*NN)/8, 256>>>(x, J, e1, 0);
  k_phaseA<<<(2*NN)/8, 256>>>(x, J, e1, 2);
  k_gram<<<dim3(SPLIT, BB), 256>>>(J);
  k_reduce1<<<dim3(16, 4, BB), 256>>>();
  k_reduce2<<<dim3(16, BB), 256>>>();
  k_tridiag<<<BB, 32>>>();
  k_bisect<<<BB, 256>>>();
  k_final<<<1, 32>>>(out);
}

// round 8
// speedup vs baseline: 1.9921x; 1.0466x over previous
#include <cuda_runtime.h>
#include <cuda_bf16.h>
#include <math.h>
#include <stdint.h>

#define BB 4
#define NN 25600
#define DD 64
#define RR (3*NN)
#define SPLIT 148
#define NPART SPLIT
#define KT 32
#define SS 72   // smem row stride (floats): conflict-free mma fragment loads

typedef unsigned long long ull;

__device__ __nv_bfloat16 g_Jb[(size_t)BB*RR*DD];
__device__ __nv_bfloat16 g_Pb[(size_t)BB*RR*DD];
__device__ __nv_bfloat16 g_Zb[(size_t)BB*RR*DD];
__device__ float g_part[(size_t)BB*NPART*DD*DD];
__device__ float g_part2[BB*4*DD*DD];
__device__ float g_M[BB*DD*DD];
__device__ float g_trace[BB];
__device__ int   g_rowptr[NN+1];

#define MMA_TF32(c, a0,a1,a2,a3, b0,b1) \
  asm("mma.sync.aligned.m16n8k8.row.col.f32.tf32.tf32.f32 " \
      "{%0,%1,%2,%3}, {%4,%5,%6,%7}, {%8,%9}, {%0,%1,%2,%3};" \
      : "+f"(c[0]),"+f"(c[1]),"+f"(c[2]),"+f"(c[3]) \
      : "r"(a0),"r"(a1),"r"(a2),"r"(a3), "r"(b0),"r"(b1))

// expand packed bf16x2 -> two f32 (exact; bf16 subset of tf32)
__device__ __forceinline__ float2 bf2f(uint32_t u){
  float2 r;
  r.x = __uint_as_float(u << 16);
  r.y = __uint_as_float(u & 0xffff0000u);
  return r;
}

// Build CSR row pointers from the lexicographically sorted e0 array.
__global__ void k_rowptr(const int* __restrict__ e0, int E){
  int i = blockIdx.x*blockDim.x + threadIdx.x;
  if(i >= E) return;
  int cur  = e0[i];
  int prev = (i==0) ? -1 : e0[i-1];
  for(int n = prev+1; n <= cur; n++) g_rowptr[n] = i;
  if(i == E-1){
    for(int n = cur+1; n <= NN; n++) g_rowptr[n] = E;
  }
}

// One warp per (batch, node): writes bf16 J copy, P = LJ, Z = Lc^{-1} BTJ.
__global__ void k_phaseA(const float* __restrict__ x, const float* __restrict__ J,
                         const int* __restrict__ e1)
{
  int gw   = (blockIdx.x*blockDim.x + threadIdx.x) >> 5;
  int lane = threadIdx.x & 31;
  if(gw >= BB*NN) return;
  int b = gw / NN;
  int n = gw - b*NN;

  const float* xb = x + (size_t)b*NN*3;
  const float* Jb = J + (size_t)b*RR*DD;
  int rs = g_rowptr[n], re = g_rowptr[n+1];
  float deg = (float)(re - rs);
  float xn0 = xb[3*n], xn1 = xb[3*n+1], xn2 = xb[3*n+2];

  float g10x=0,g10y=0,g11x=0,g11y=0,g12x=0,g12y=0;
  float g20x=0,g20y=0,g21x=0,g21y=0,g22x=0,g22y=0;
  float c00=0,c11=0,c22=0,c01=0,c02=0,c12=0;
  float vs0=0,vs1=0,vs2=0;

  for(int e = rs; e < re; e++){
    int m = e1[e];
    float v0 = xn0 - xb[3*m];
    float v1 = xn1 - xb[3*m+1];
    float v2 = xn2 - xb[3*m+2];
    const float2* Jm = reinterpret_cast<const float2*>(Jb + (size_t)m*192);
    float2 j0 = Jm[lane];
    float2 j1 = Jm[32+lane];
    float2 j2 = Jm[64+lane];
    g10x += j0.x; g10y += j0.y;
    g11x += j1.x; g11y += j1.y;
    g12x += j2.x; g12y += j2.y;
    g20x += v1*j2.x - v2*j1.x;  g20y += v1*j2.y - v2*j1.y;
    g21x += v2*j0.x - v0*j2.x;  g21y += v2*j0.y - v0*j2.y;
    g22x += v0*j1.x - v1*j0.x;  g22y += v0*j1.y - v1*j0.y;
    float vv = v0*v0 + v1*v1 + v2*v2;
    c00 += vv - v0*v0;
    c11 += vv - v1*v1;
    c22 += vv - v2*v2;
    c01 -= v0*v1; c02 -= v0*v2; c12 -= v1*v2;
    vs0 += v0; vs1 += v1; vs2 += v2;
  }

  const float2* Jn = reinterpret_cast<const float2*>(Jb + (size_t)n*192);
  float2 a0 = Jn[lane], a1 = Jn[32+lane], a2 = Jn[64+lane];

  size_t rowbase = ((size_t)b*NN + n)*192;

  __nv_bfloat162* Jbp = reinterpret_cast<__nv_bfloat162*>(g_Jb + rowbase);
  Jbp[lane]    = __floats2bfloat162_rn(a0.x, a0.y);
  Jbp[32+lane] = __floats2bfloat162_rn(a1.x, a1.y);
  Jbp[64+lane] = __floats2bfloat162_rn(a2.x, a2.y);

  __nv_bfloat162* Pp = reinterpret_cast<__nv_bfloat162*>(g_Pb + rowbase);
  Pp[lane]    = __floats2bfloat162_rn(2.f*(deg*a0.x - g10x), 2.f*(deg*a0.y - g10y));
  Pp[32+lane] = __floats2bfloat162_rn(2.f*(deg*a1.x - g11x), 2.f*(deg*a1.y - g11y));
  Pp[64+lane] = __floats2bfloat162_rn(2.f*(deg*a2.x - g12x), 2.f*(deg*a2.y - g12y));

  float q0x = g20x - (vs1*a2.x - vs2*a1.x);
  float q0y = g20y - (vs1*a2.y - vs2*a1.y);
  float q1x = g21x - (vs2*a0.x - vs0*a2.x);
  float q1y = g21y - (vs2*a0.y - vs0*a2.y);
  float q2x = g22x - (vs0*a1.x - vs1*a0.x);
  float q2y = g22y - (vs0*a1.y - vs1*a0.y);

  float l00 = sqrtf(fmaxf(c00, 1e-30f));
  float i00 = 1.f/l00;
  float l10 = c01*i00, l20 = c02*i00;
  float l11 = sqrtf(fmaxf(c11 - l10*l10, 1e-30f));
  float i11 = 1.f/l11;
  float l21 = (c12 - l20*l10)*i11;
  float l22 = sqrtf(fmaxf(c22 - l20*l20 - l21*l21, 1e-30f));
  float i22 = 1.f/l22;

  float z0x = q0x*i00,                          z0y = q0y*i00;
  float z1x = (q1x - l10*z0x)*i11,              z1y = (q1y - l10*z0y)*i11;
  float z2x = (q2x - l20*z0x - l21*z1x)*i22,    z2y = (q2y - l20*z0y - l21*z1y)*i22;

  __nv_bfloat162* Zp = reinterpret_cast<__nv_bfloat162*>(g_Zb + rowbase);
  Zp[lane]    = __floats2bfloat162_rn(z0x, z0y);
  Zp[32+lane] = __floats2bfloat162_rn(z1x, z1y);
  Zp[64+lane] = __floats2bfloat162_rn(z2x, z2y);
}

// M_partial = J^T P - Z^T Z via tf32 tensor-core mma (m16n8k8), bf16 inputs.
__global__ void __launch_bounds__(256) k_gram(){
  __shared__ __align__(16) float sJ[KT*SS];
  __shared__ __align__(16) float sP[KT*SS];
  __shared__ __align__(16) float sZ[KT*SS];
  int b    = blockIdx.y;
  int tid  = threadIdx.x;
  int w    = tid >> 5;
  int lane = tid & 31;
  int g    = lane >> 2;
  int t    = lane & 3;
  int ib   = (w >> 1) * 16;
  int jb   = (w & 1) * 32;

  const uint4* gJ = reinterpret_cast<const uint4*>(g_Jb + (size_t)b*RR*DD);
  const uint4* gP = reinterpret_cast<const uint4*>(g_Pb + (size_t)b*RR*DD);
  const uint4* gZ = reinterpret_cast<const uint4*>(g_Zb + (size_t)b*RR*DD);

  float accJ[4][4], accZ[4][4];
  #pragma unroll
  for(int s=0;s<4;s++)
    #pragma unroll
    for(int r=0;r<4;r++){ accJ[s][r]=0.f; accZ[s][r]=0.f; }

  const int ntiles = RR/KT;   // 2400
  for(int tt = blockIdx.x; tt < ntiles; tt += SPLIT){
    size_t base = (size_t)tt*256;      // 256 uint4 (8 bf16 each) per tile per array
    __syncthreads();
    {
      int k  = tid >> 3;               // 0..31
      int c8 = (tid & 7) * 8;          // 0..56
      int so = k*SS + c8;
      uint4 vj = gJ[base + tid];
      uint4 vp = gP[base + tid];
      uint4 vz = gZ[base + tid];
      float2 f0, f1, f2, f3;
      f0 = bf2f(vj.x); f1 = bf2f(vj.y); f2 = bf2f(vj.z); f3 = bf2f(vj.w);
      *reinterpret_cast<float4*>(sJ + so)     = make_float4(f0.x,f0.y,f1.x,f1.y);
      *reinterpret_cast<float4*>(sJ + so + 4) = make_float4(f2.x,f2.y,f3.x,f3.y);
      f0 = bf2f(vp.x); f1 = bf2f(vp.y); f2 = bf2f(vp.z); f3 = bf2f(vp.w);
      *reinterpret_cast<float4*>(sP + so)     = make_float4(f0.x,f0.y,f1.x,f1.y);
      *reinterpret_cast<float4*>(sP + so + 4) = make_float4(f2.x,f2.y,f3.x,f3.y);
      f0 = bf2f(vz.x); f1 = bf2f(vz.y); f2 = bf2f(vz.z); f3 = bf2f(vz.w);
      *reinterpret_cast<float4*>(sZ + so)     = make_float4(f0.x,f0.y,f1.x,f1.y);
      *reinterpret_cast<float4*>(sZ + so + 4) = make_float4(f2.x,f2.y,f3.x,f3.y);
    }
    __syncthreads();
    #pragma unroll
    for(int k8 = 0; k8 < 4; k8++){
      int kb = k8*8;
      int rlo = (kb+t)*SS, rhi = (kb+t+4)*SS;
      uint32_t aj0 = __float_as_uint(sJ[rlo + ib + g]);
      uint32_t aj1 = __float_as_uint(sJ[rlo + ib + g + 8]);
      uint32_t aj2 = __float_as_uint(sJ[rhi + ib + g]);
      uint32_t aj3 = __float_as_uint(sJ[rhi + ib + g + 8]);
      uint32_t az0 = __float_as_uint(sZ[rlo + ib + g]);
      uint32_t az1 = __float_as_uint(sZ[rlo + ib + g + 8]);
      uint32_t az2 = __float_as_uint(sZ[rhi + ib + g]);
      uint32_t az3 = __float_as_uint(sZ[rhi + ib + g + 8]);
      #pragma unroll
      for(int s = 0; s < 4; s++){
        int j0 = jb + s*8;
        uint32_t bp0 = __float_as_uint(sP[rlo + j0 + g]);
        uint32_t bp1 = __float_as_uint(sP[rhi + j0 + g]);
        uint32_t bz0 = __float_as_uint(sZ[rlo + j0 + g]);
        uint32_t bz1 = __float_as_uint(sZ[rhi + j0 + g]);
        MMA_TF32(accJ[s], aj0,aj1,aj2,aj3, bp0,bp1);
        MMA_TF32(accZ[s], az0,az1,az2,az3, bz0,bz1);
      }
    }
  }

  float* outp = g_part + ((size_t)b*NPART + blockIdx.x)*DD*DD;
  int row = ib + g;
  #pragma unroll
  for(int s = 0; s < 4; s++){
    int col = jb + s*8 + 2*t;
    outp[row*64 + col]       = accJ[s][0] - accZ[s][0];
    outp[row*64 + col + 1]   = accJ[s][1] - accZ[s][1];
    outp[(row+8)*64 + col]   = accJ[s][2] - accZ[s][2];
    outp[(row+8)*64 + col+1] = accJ[s][3] - accZ[s][3];
  }
}

// Two-stage deterministic reduction of the 148 partials per batch.
__global__ void k_reduce1(){
  int elem = blockIdx.x*256 + threadIdx.x;
  int grp  = blockIdx.y;
  int b    = blockIdx.z;
  const float* base = g_part + (size_t)b*NPART*4096 + elem;
  int s = grp*37;
  float a0=0.f, a1=0.f, a2=0.f, a3=0.f;
  #pragma unroll
  for(int i = 0; i < 36; i += 4){
    a0 += base[(size_t)(s+i  )*4096];
    a1 += base[(size_t)(s+i+1)*4096];
    a2 += base[(size_t)(s+i+2)*4096];
    a3 += base[(size_t)(s+i+3)*4096];
  }
  a0 += base[(size_t)(s+36)*4096];
  g_part2[((b*4 + grp)*4096) + elem] = (a0+a1) + (a2+a3);
}

__global__ void k_reduce2(){
  int elem = blockIdx.x*256 + threadIdx.x;
  int b    = blockIdx.y;
  float v = g_part2[(b*4+0)*4096 + elem]
          + g_part2[(b*4+1)*4096 + elem]
          + g_part2[(b*4+2)*4096 + elem]
          + g_part2[(b*4+3)*4096 + elem];
  g_M[b*4096 + elem] = v;
}

// Fused eigensolver: warp 0 tridiagonalizes (Householder, float4 inner loops),
// then all 256 threads run 4-way multisection per eigenvalue.
__global__ void __launch_bounds__(256) k_eig(){
  __shared__ __align__(16) float s[64][68];
  __shared__ __align__(16) float vc[64], wc[64];
  __shared__ float ee[64];
  __shared__ float dd[64], e2s[64];
  __shared__ float bnd[2];
  __shared__ float red[64];
  int b = blockIdx.x;
  int tid = threadIdx.x;

  if(tid < 32){
    int lane = tid;
    const float* Mb = g_M + b*4096;
    for(int i = lane; i < 4096; i += 32){
      int r = i >> 6, c = i & 63;
      s[r][c] = 0.5f*(Mb[r*64+c] + Mb[c*64+r]);
    }
    __syncwarp();

    for(int k = 0; k < 31; k++){
      int m = 63 - k;
      int cb = (k + 1) & ~15;
      int nq = (64 - cb) >> 2;
      int r0 = k + 1 + lane;
      bool a1 = (lane + 32 < m);
      int r1v = r0 + 32;
      int r1 = a1 ? r1v : 63;
      float x0 = s[r0][k];
      float x1 = a1 ? s[r1v][k] : 0.f;
      float n2 = x0*x0 + x1*x1;
      #pragma unroll
      for(int o = 16; o > 0; o >>= 1) n2 += __shfl_xor_sync(0xffffffffu, n2, o);
      float x00 = __shfl_sync(0xffffffffu, x0, 0);
      float alpha, beta;
      if(n2 < 1e-28f){ alpha = x00; beta = 0.f; }
      else {
        alpha = (x00 >= 0.f) ? -sqrtf(n2) : sqrtf(n2);
        beta  = 1.f/(n2 - alpha*x00);
      }
      if(lane == 0) ee[k] = alpha;
      if(beta != 0.f){
        float v0 = (lane == 0) ? (x00 - alpha) : x0;
        float v1 = a1 ? x1 : 0.f;
        int c0 = cb + lane;
        if(c0 <= k) vc[c0] = 0.f;
        vc[k+1+lane] = v0;
        int c2 = k + 33 + lane;
        if(c2 < 64) vc[c2] = v1;
        __syncwarp();

        const float4* row04 = reinterpret_cast<const float4*>(&s[r0][0]);
        const float4* row14 = reinterpret_cast<const float4*>(&s[r1][0]);
        const float4* vc4   = reinterpret_cast<const float4*>(vc);
        float pA=0.f, pB=0.f, pC=0.f, pD=0.f;
        float qA=0.f, qB=0.f, qC=0.f, qD=0.f;
        int q0 = cb >> 2;
        #pragma unroll 4
        for(int q = 0; q < nq; q += 4){
          float4 vA = vc4[q0+q],   vB = vc4[q0+q+1], vC = vc4[q0+q+2], vD = vc4[q0+q+3];
          float4 rA = row04[q0+q], rB = row04[q0+q+1], rC = row04[q0+q+2], rD = row04[q0+q+3];
          float4 sA = row14[q0+q], sB = row14[q0+q+1], sC = row14[q0+q+2], sD = row14[q0+q+3];
          pA = fmaf(rA.x,vA.x,fmaf(rA.y,vA.y,fmaf(rA.z,vA.z,fmaf(rA.w,vA.w,pA))));
          pB = fmaf(rB.x,vB.x,fmaf(rB.y,vB.y,fmaf(rB.z,vB.z,fmaf(rB.w,vB.w,pB))));
          pC = fmaf(rC.x,vC.x,fmaf(rC.y,vC.y,fmaf(rC.z,vC.z,fmaf(rC.w,vC.w,pC))));
          pD = fmaf(rD.x,vD.x,fmaf(rD.y,vD.y,fmaf(rD.z,vD.z,fmaf(rD.w,vD.w,pD))));
          qA = fmaf(sA.x,vA.x,fmaf(sA.y,vA.y,fmaf(sA.z,vA.z,fmaf(sA.w,vA.w,qA))));
          qB = fmaf(sB.x,vB.x,fmaf(sB.y,vB.y,fmaf(sB.z,vB.z,fmaf(sB.w,vB.w,qB))));
          qC = fmaf(sC.x,vC.x,fmaf(sC.y,vC.y,fmaf(sC.z,vC.z,fmaf(sC.w,vC.w,qC))));
          qD = fmaf(sD.x,vD.x,fmaf(sD.y,vD.y,fmaf(sD.z,vD.z,fmaf(sD.w,vD.w,qD))));
        }
        float p0 = beta*((pA+pB) + (pC+pD));
        float p1 = beta*((qA+qB) + (qC+qD));
        float ptv = p0*v0 + p1*v1;
        #pragma unroll
        for(int o = 16; o > 0; o >>= 1) ptv += __shfl_xor_sync(0xffffffffu, ptv, o);
        float K = 0.5f*beta*ptv;
        float w0 = p0 - K*v0;
        float w1 = a1 ? (p1 - K*v1) : 0.f;
        if(c0 <= k) wc[c0] = 0.f;
        wc[k+1+lane] = w0;
        if(c2 < 64) wc[c2] = w1;
        __syncwarp();

        float4* u04 = reinterpret_cast<float4*>(&s[r0][0]);
        const float4* wc4 = reinterpret_cast<const float4*>(wc);
        #pragma unroll 4
        for(int q = q0; q < q0 + nq; q++){
          float4 vq = vc4[q], wq = wc4[q];
          float4 r = u04[q];
          r.x -= v0*wq.x + w0*vq.x;
          r.y -= v0*wq.y + w0*vq.y;
          r.z -= v0*wq.z + w0*vq.z;
          r.w -= v0*wq.w + w0*vq.w;
          u04[q] = r;
        }
        if(a1){
          float4* u14 = reinterpret_cast<float4*>(&s[r1v][0]);
          #pragma unroll 4
          for(int q = q0; q < q0 + nq; q++){
            float4 vq = vc4[q], wq = wc4[q];
            float4 r = u14[q];
            r.x -= v1*wq.x + w1*vq.x;
            r.y -= v1*wq.y + w1*vq.y;
            r.z -= v1*wq.z + w1*vq.z;
            r.w -= v1*wq.w + w1*vq.w;
            u14[q] = r;
          }
        }
        __syncwarp();
      }
    }

    for(int k = 31; k < 62; k++){
      int m = 63 - k;
      int cb = (k + 1) & ~15;
      int nq = (64 - cb) >> 2;
      bool a0 = (lane < m);
      int r0v = k + 1 + lane;
      int r0 = a0 ? r0v : 63;
      float x0 = a0 ? s[r0v][k] : 0.f;
      float n2 = x0*x0;
      #pragma unroll
      for(int o = 16; o > 0; o >>= 1) n2 += __shfl_xor_sync(0xffffffffu, n2, o);
      float x00 = __shfl_sync(0xffffffffu, x0, 0);
      float alpha, beta;
      if(n2 < 1e-28f){ alpha = x00; beta = 0.f; }
      else {
        alpha = (x00 >= 0.f) ? -sqrtf(n2) : sqrtf(n2);
        beta  = 1.f/(n2 - alpha*x00);
      }
      if(lane == 0) ee[k] = alpha;
      if(beta != 0.f){
        float v0 = a0 ? ((lane == 0) ? (x00 - alpha) : x0) : 0.f;
        int c0 = cb + lane;
        if(c0 <= k) vc[c0] = 0.f;
        int c1 = k + 1 + lane;
        if(c1 < 64) vc[c1] = v0;
        __syncwarp();

        const float4* row04 = reinterpret_cast<const float4*>(&s[r0][0]);
        const float4* vc4   = reinterpret_cast<const float4*>(vc);
        float pA=0.f, pB=0.f, pC=0.f, pD=0.f;
        int q0 = cb >> 2;
        #pragma unroll 4
        for(int q = 0; q < nq; q += 4){
          float4 vA = vc4[q0+q],   vB = vc4[q0+q+1], vC = vc4[q0+q+2], vD = vc4[q0+q+3];
          float4 rA = row04[q0+q], rB = row04[q0+q+1], rC = row04[q0+q+2], rD = row04[q0+q+3];
          pA = fmaf(rA.x,vA.x,fmaf(rA.y,vA.y,fmaf(rA.z,vA.z,fmaf(rA.w,vA.w,pA))));
          pB = fmaf(rB.x,vB.x,fmaf(rB.y,vB.y,fmaf(rB.z,vB.z,fmaf(rB.w,vB.w,pB))));
          pC = fmaf(rC.x,vC.x,fmaf(rC.y,vC.y,fmaf(rC.z,vC.z,fmaf(rC.w,vC.w,pC))));
          pD = fmaf(rD.x,vD.x,fmaf(rD.y,vD.y,fmaf(rD.z,vD.z,fmaf(rD.w,vD.w,pD))));
        }
        float p0 = beta*((pA+pB) + (pC+pD));
        float ptv = p0*v0;
        #pragma unroll
        for(int o = 16; o > 0; o >>= 1) ptv += __shfl_xor_sync(0xffffffffu, ptv, o);
        float K = 0.5f*beta*ptv;
        float w0 = a0 ? (p0 - K*v0) : 0.f;
        if(c0 <= k) wc[c0] = 0.f;
        if(c1 < 64) wc[c1] = w0;
        __syncwarp();

        if(a0){
          float4* u04 = reinterpret_cast<float4*>(&s[r0v][0]);
          const float4* wc4 = reinterpret_cast<const float4*>(wc);
          #pragma unroll 4
          for(int q = q0; q < q0 + nq; q++){
            float4 vq = vc4[q], wq = wc4[q];
            float4 r = u04[q];
            r.x -= v0*wq.x + w0*vq.x;
            r.y -= v0*wq.y + w0*vq.y;
            r.z -= v0*wq.z + w0*vq.z;
            r.w -= v0*wq.w + w0*vq.w;
            u04[q] = r;
          }
        }
        __syncwarp();
      }
    }

    if(lane == 0) ee[62] = s[63][62];
    __syncwarp();
    dd[lane]      = s[lane][lane];
    dd[lane + 32] = s[lane+32][lane+32];
    float eA = (lane < 31) ? ee[lane] : 0.f;
    if(lane < 31) e2s[lane] = eA*eA;
    float eB = ee[31 + lane];
    e2s[31 + lane] = eB*eB;
    if(lane == 0) e2s[63] = 0.f;
  }
  __syncthreads();

  // Gershgorin bounds
  if(tid < 64){
    float el = (tid > 0)  ? sqrtf(e2s[tid-1]) : 0.f;
    float er = (tid < 63) ? sqrtf(e2s[tid])   : 0.f;
    vc[tid] = dd[tid] - el - er;
    wc[tid] = dd[tid] + el + er;
  }
  __syncthreads();
  if(tid < 32){
    float lo = fminf(vc[tid], vc[tid+32]);
    float hi = fmaxf(wc[tid], wc[tid+32]);
    #pragma unroll
    for(int o = 16; o > 0; o >>= 1){
      lo = fminf(lo, __shfl_down_sync(0xffffffffu, lo, o));
      hi = fmaxf(hi, __shfl_down_sync(0xffffffffu, hi, o));
    }
    if(tid == 0){ bnd[0] = lo; bnd[1] = hi; }
  }
  __syncthreads();

  int j = tid >> 2;
  int t = tid & 3;
  int wl = tid & 31;
  unsigned base = wl & ~3u;
  float lo = bnd[0], hi = bnd[1];

  #pragma unroll 1
  for(int r = 0; r < 10; r++){
    float mid = lo + (hi - lo)*0.2f*(float)(t+1);
    int cnt = 0;
    float q = dd[0] - mid;
    cnt += (q < 0.f);
    #pragma unroll 1
    for(int i = 1; i < 64; i++){
      float aq = fabsf(q);
      float denom = (aq < 1e-25f) ? ((q < 0.f) ? -1e-25f : 1e-25f) : q;
      q = (dd[i] - mid) - __fdividef(e2s[i-1], denom);
      cnt += (q < 0.f);
    }
    int less = (cnt > j);
    #pragma unroll
    for(int s2 = 0; s2 < 4; s2++){
      float ms = __shfl_sync(0xffffffffu, mid,  base + s2);
      int   ls = __shfl_sync(0xffffffffu, less, base + s2);
      if(ls) hi = fminf(hi, ms); else lo = fmaxf(lo, ms);
    }
  }

  float lam = 0.5f*(lo + hi);
  float val = (t == 0 && lam > 0.f) ? sqrtf(lam) : 0.f;
  #pragma unroll
  for(int o = 16; o > 0; o >>= 1) val += __shfl_down_sync(0xffffffffu, val, o);
  if(wl == 0) red[tid >> 5] = val;
  __syncthreads();
  if(tid == 0){
    float sum = 0.f;
    #pragma unroll
    for(int w = 0; w < 8; w++) sum += red[w];
    g_trace[b] = sum;
  }
}

__global__ void k_final(float* out){
  if(threadIdx.x == 0)
    out[0] = 0.25f*(g_trace[0] + g_trace[1] + g_trace[2] + g_trace[3]);
}

extern "C" void kernel_launch(void* const* d_in, const int* in_sizes, int n_in,
                              void* d_out, int out_size){
  const float* x  = (const float*)d_in[0];
  const float* J  = (const float*)d_in[1];
  const int*   e0 = (const int*)d_in[2];
  const int*   e1 = (const int*)d_in[3];
  int E = in_sizes[2];
  float* out = (float*)d_out;

  k_rowptr<<<(E + 255)/256, 256>>>(e0, E);
  k_phaseA<<<(BB*NN)/8, 256>>>(x, J, e1);
  k_gram<<<dim3(SPLIT, BB), 256>>>();
  k_reduce1<<<dim3(16, 4, BB), 256>>>();
  k_reduce2<<<dim3(16, BB), 256>>>();
  k_eig<<<BB, 256>>>();
  k_final<<<1, 32>>>(out);
}

// round 9
// speedup vs baseline: 2.0212x; 1.0146x over previous
#include <cuda_runtime.h>
#include <cuda_bf16.h>
#include <math.h>
#include <stdint.h>

#define BB 4
#define NN 25600
#define DD 64
#define RR (3*NN)
#define SPLIT 148
#define NPART SPLIT
#define KT 32
#define SS 72   // smem row stride (floats): conflict-free mma fragment loads

typedef unsigned long long ull;

__device__ __nv_bfloat16 g_Jb[(size_t)BB*RR*DD];
__device__ __nv_bfloat16 g_Pb[(size_t)BB*RR*DD];
__device__ __nv_bfloat16 g_Zb[(size_t)BB*RR*DD];
__device__ float g_part[(size_t)BB*NPART*DD*DD];
__device__ float g_part2[BB*4*DD*DD];
__device__ float g_M[BB*DD*DD];
__device__ float g_trace[BB];
__device__ int   g_rowptr[NN+1];

#define MMA_TF32(c, a0,a1,a2,a3, b0,b1) \
  asm("mma.sync.aligned.m16n8k8.row.col.f32.tf32.tf32.f32 " \
      "{%0,%1,%2,%3}, {%4,%5,%6,%7}, {%8,%9}, {%0,%1,%2,%3};" \
      : "+f"(c[0]),"+f"(c[1]),"+f"(c[2]),"+f"(c[3]) \
      : "r"(a0),"r"(a1),"r"(a2),"r"(a3), "r"(b0),"r"(b1))

// expand packed bf16x2 -> two f32 (exact; bf16 subset of tf32)
__device__ __forceinline__ float2 bf2f(uint32_t u){
  float2 r;
  r.x = __uint_as_float(u << 16);
  r.y = __uint_as_float(u & 0xffff0000u);
  return r;
}

// Build CSR row pointers from the lexicographically sorted e0 array.
__global__ void k_rowptr(const int* __restrict__ e0, int E){
  int i = blockIdx.x*blockDim.x + threadIdx.x;
  if(i >= E) return;
  int cur  = e0[i];
  int prev = (i==0) ? -1 : e0[i-1];
  for(int n = prev+1; n <= cur; n++) g_rowptr[n] = i;
  if(i == E-1){
    for(int n = cur+1; n <= NN; n++) g_rowptr[n] = E;
  }
}

// One warp per (batch, node): writes bf16 J copy, P = LJ, Z = Lc^{-1} BTJ.
__global__ void k_phaseA(const float* __restrict__ x, const float* __restrict__ J,
                         const int* __restrict__ e1)
{
  int gw   = (blockIdx.x*blockDim.x + threadIdx.x) >> 5;
  int lane = threadIdx.x & 31;
  if(gw >= BB*NN) return;
  int b = gw / NN;
  int n = gw - b*NN;

  const float* xb = x + (size_t)b*NN*3;
  const float* Jb = J + (size_t)b*RR*DD;
  int rs = g_rowptr[n], re = g_rowptr[n+1];
  float deg = (float)(re - rs);
  float xn0 = xb[3*n], xn1 = xb[3*n+1], xn2 = xb[3*n+2];

  float g10x=0,g10y=0,g11x=0,g11y=0,g12x=0,g12y=0;
  float g20x=0,g20y=0,g21x=0,g21y=0,g22x=0,g22y=0;
  float c00=0,c11=0,c22=0,c01=0,c02=0,c12=0;
  float vs0=0,vs1=0,vs2=0;

  for(int e = rs; e < re; e++){
    int m = e1[e];
    float v0 = xn0 - xb[3*m];
    float v1 = xn1 - xb[3*m+1];
    float v2 = xn2 - xb[3*m+2];
    const float2* Jm = reinterpret_cast<const float2*>(Jb + (size_t)m*192);
    float2 j0 = Jm[lane];
    float2 j1 = Jm[32+lane];
    float2 j2 = Jm[64+lane];
    g10x += j0.x; g10y += j0.y;
    g11x += j1.x; g11y += j1.y;
    g12x += j2.x; g12y += j2.y;
    g20x += v1*j2.x - v2*j1.x;  g20y += v1*j2.y - v2*j1.y;
    g21x += v2*j0.x - v0*j2.x;  g21y += v2*j0.y - v0*j2.y;
    g22x += v0*j1.x - v1*j0.x;  g22y += v0*j1.y - v1*j0.y;
    float vv = v0*v0 + v1*v1 + v2*v2;
    c00 += vv - v0*v0;
    c11 += vv - v1*v1;
    c22 += vv - v2*v2;
    c01 -= v0*v1; c02 -= v0*v2; c12 -= v1*v2;
    vs0 += v0; vs1 += v1; vs2 += v2;
  }

  const float2* Jn = reinterpret_cast<const float2*>(Jb + (size_t)n*192);
  float2 a0 = Jn[lane], a1 = Jn[32+lane], a2 = Jn[64+lane];

  size_t rowbase = ((size_t)b*NN + n)*192;

  __nv_bfloat162* Jbp = reinterpret_cast<__nv_bfloat162*>(g_Jb + rowbase);
  Jbp[lane]    = __floats2bfloat162_rn(a0.x, a0.y);
  Jbp[32+lane] = __floats2bfloat162_rn(a1.x, a1.y);
  Jbp[64+lane] = __floats2bfloat162_rn(a2.x, a2.y);

  __nv_bfloat162* Pp = reinterpret_cast<__nv_bfloat162*>(g_Pb + rowbase);
  Pp[lane]    = __floats2bfloat162_rn(2.f*(deg*a0.x - g10x), 2.f*(deg*a0.y - g10y));
  Pp[32+lane] = __floats2bfloat162_rn(2.f*(deg*a1.x - g11x), 2.f*(deg*a1.y - g11y));
  Pp[64+lane] = __floats2bfloat162_rn(2.f*(deg*a2.x - g12x), 2.f*(deg*a2.y - g12y));

  float q0x = g20x - (vs1*a2.x - vs2*a1.x);
  float q0y = g20y - (vs1*a2.y - vs2*a1.y);
  float q1x = g21x - (vs2*a0.x - vs0*a2.x);
  float q1y = g21y - (vs2*a0.y - vs0*a2.y);
  float q2x = g22x - (vs0*a1.x - vs1*a0.x);
  float q2y = g22y - (vs0*a1.y - vs1*a0.y);

  float l00 = sqrtf(fmaxf(c00, 1e-30f));
  float i00 = 1.f/l00;
  float l10 = c01*i00, l20 = c02*i00;
  float l11 = sqrtf(fmaxf(c11 - l10*l10, 1e-30f));
  float i11 = 1.f/l11;
  float l21 = (c12 - l20*l10)*i11;
  float l22 = sqrtf(fmaxf(c22 - l20*l20 - l21*l21, 1e-30f));
  float i22 = 1.f/l22;

  float z0x = q0x*i00,                          z0y = q0y*i00;
  float z1x = (q1x - l10*z0x)*i11,              z1y = (q1y - l10*z0y)*i11;
  float z2x = (q2x - l20*z0x - l21*z1x)*i22,    z2y = (q2y - l20*z0y - l21*z1y)*i22;

  __nv_bfloat162* Zp = reinterpret_cast<__nv_bfloat162*>(g_Zb + rowbase);
  Zp[lane]    = __floats2bfloat162_rn(z0x, z0y);
  Zp[32+lane] = __floats2bfloat162_rn(z1x, z1y);
  Zp[64+lane] = __floats2bfloat162_rn(z2x, z2y);
}

// M_partial = J^T P - Z^T Z via tf32 tensor-core mma (m16n8k8), bf16 inputs.
__global__ void __launch_bounds__(256) k_gram(){
  __shared__ __align__(16) float sJ[KT*SS];
  __shared__ __align__(16) float sP[KT*SS];
  __shared__ __align__(16) float sZ[KT*SS];
  int b    = blockIdx.y;
  int tid  = threadIdx.x;
  int w    = tid >> 5;
  int lane = tid & 31;
  int g    = lane >> 2;
  int t    = lane & 3;
  int ib   = (w >> 1) * 16;
  int jb   = (w & 1) * 32;

  const uint4* gJ = reinterpret_cast<const uint4*>(g_Jb + (size_t)b*RR*DD);
  const uint4* gP = reinterpret_cast<const uint4*>(g_Pb + (size_t)b*RR*DD);
  const uint4* gZ = reinterpret_cast<const uint4*>(g_Zb + (size_t)b*RR*DD);

  float accJ[4][4], accZ[4][4];
  #pragma unroll
  for(int s=0;s<4;s++)
    #pragma unroll
    for(int r=0;r<4;r++){ accJ[s][r]=0.f; accZ[s][r]=0.f; }

  const int ntiles = RR/KT;   // 2400
  for(int tt = blockIdx.x; tt < ntiles; tt += SPLIT){
    size_t base = (size_t)tt*256;
    __syncthreads();
    {
      int k  = tid >> 3;
      int c8 = (tid & 7) * 8;
      int so = k*SS + c8;
      uint4 vj = gJ[base + tid];
      uint4 vp = gP[base + tid];
      uint4 vz = gZ[base + tid];
      float2 f0, f1, f2, f3;
      f0 = bf2f(vj.x); f1 = bf2f(vj.y); f2 = bf2f(vj.z); f3 = bf2f(vj.w);
      *reinterpret_cast<float4*>(sJ + so)     = make_float4(f0.x,f0.y,f1.x,f1.y);
      *reinterpret_cast<float4*>(sJ + so + 4) = make_float4(f2.x,f2.y,f3.x,f3.y);
      f0 = bf2f(vp.x); f1 = bf2f(vp.y); f2 = bf2f(vp.z); f3 = bf2f(vp.w);
      *reinterpret_cast<float4*>(sP + so)     = make_float4(f0.x,f0.y,f1.x,f1.y);
      *reinterpret_cast<float4*>(sP + so + 4) = make_float4(f2.x,f2.y,f3.x,f3.y);
      f0 = bf2f(vz.x); f1 = bf2f(vz.y); f2 = bf2f(vz.z); f3 = bf2f(vz.w);
      *reinterpret_cast<float4*>(sZ + so)     = make_float4(f0.x,f0.y,f1.x,f1.y);
      *reinterpret_cast<float4*>(sZ + so + 4) = make_float4(f2.x,f2.y,f3.x,f3.y);
    }
    __syncthreads();
    #pragma unroll
    for(int k8 = 0; k8 < 4; k8++){
      int kb = k8*8;
      int rlo = (kb+t)*SS, rhi = (kb+t+4)*SS;
      uint32_t aj0 = __float_as_uint(sJ[rlo + ib + g]);
      uint32_t aj1 = __float_as_uint(sJ[rlo + ib + g + 8]);
      uint32_t aj2 = __float_as_uint(sJ[rhi + ib + g]);
      uint32_t aj3 = __float_as_uint(sJ[rhi + ib + g + 8]);
      uint32_t az0 = __float_as_uint(sZ[rlo + ib + g]);
      uint32_t az1 = __float_as_uint(sZ[rlo + ib + g + 8]);
      uint32_t az2 = __float_as_uint(sZ[rhi + ib + g]);
      uint32_t az3 = __float_as_uint(sZ[rhi + ib + g + 8]);
      #pragma unroll
      for(int s = 0; s < 4; s++){
        int j0 = jb + s*8;
        uint32_t bp0 = __float_as_uint(sP[rlo + j0 + g]);
        uint32_t bp1 = __float_as_uint(sP[rhi + j0 + g]);
        uint32_t bz0 = __float_as_uint(sZ[rlo + j0 + g]);
        uint32_t bz1 = __float_as_uint(sZ[rhi + j0 + g]);
        MMA_TF32(accJ[s], aj0,aj1,aj2,aj3, bp0,bp1);
        MMA_TF32(accZ[s], az0,az1,az2,az3, bz0,bz1);
      }
    }
  }

  float* outp = g_part + ((size_t)b*NPART + blockIdx.x)*DD*DD;
  int row = ib + g;
  #pragma unroll
  for(int s = 0; s < 4; s++){
    int col = jb + s*8 + 2*t;
    outp[row*64 + col]       = accJ[s][0] - accZ[s][0];
    outp[row*64 + col + 1]   = accJ[s][1] - accZ[s][1];
    outp[(row+8)*64 + col]   = accJ[s][2] - accZ[s][2];
    outp[(row+8)*64 + col+1] = accJ[s][3] - accZ[s][3];
  }
}

// Two-stage deterministic reduction of the 148 partials per batch.
__global__ void k_reduce1(){
  int elem = blockIdx.x*256 + threadIdx.x;
  int grp  = blockIdx.y;
  int b    = blockIdx.z;
  const float* base = g_part + (size_t)b*NPART*4096 + elem;
  int s = grp*37;
  float a0=0.f, a1=0.f, a2=0.f, a3=0.f;
  #pragma unroll
  for(int i = 0; i < 36; i += 4){
    a0 += base[(size_t)(s+i  )*4096];
    a1 += base[(size_t)(s+i+1)*4096];
    a2 += base[(size_t)(s+i+2)*4096];
    a3 += base[(size_t)(s+i+3)*4096];
  }
  a0 += base[(size_t)(s+36)*4096];
  g_part2[((b*4 + grp)*4096) + elem] = (a0+a1) + (a2+a3);
}

__global__ void k_reduce2(){
  int elem = blockIdx.x*256 + threadIdx.x;
  int b    = blockIdx.y;
  float v = g_part2[(b*4+0)*4096 + elem]
          + g_part2[(b*4+1)*4096 + elem]
          + g_part2[(b*4+2)*4096 + elem]
          + g_part2[(b*4+3)*4096 + elem];
  g_M[b*4096 + elem] = v;
}

// Fused eigensolver: BLOCK-PARALLEL Householder tridiagonalization
// (one 4-thread group per row), then 4-way multisection bisection.
__global__ void __launch_bounds__(256) k_eig(){
  __shared__ __align__(16) float s[64][68];
  __shared__ __align__(16) float vc[64], wc[64], pv[64];
  __shared__ float ee[64], dd[64], e2s[64];
  __shared__ float sc[4];          // alpha, beta, x00, K
  __shared__ float bnd[2];
  __shared__ float red[64];
  int b   = blockIdx.x;
  int tid = threadIdx.x;
  int g   = tid >> 2;              // row group 0..63
  int t   = tid & 3;               // thread in group

  const float* Mb = g_M + b*4096;
  for(int i = tid; i < 4096; i += 256){
    int r = i >> 6, c = i & 63;
    s[r][c] = 0.5f*(Mb[r*64+c] + Mb[c*64+r]);
  }
  __syncthreads();

  const float4* vc4 = reinterpret_cast<const float4*>(vc);
  const float4* wc4 = reinterpret_cast<const float4*>(wc);

  for(int k = 0; k < 62; k++){
    // 1. norm of trailing column k (warp 0)
    if(tid < 32){
      int r1 = k + 1 + tid;
      int r2 = k + 33 + tid;
      float x1 = (r1 < 64) ? s[r1][k] : 0.f;
      float x2 = (r2 < 64) ? s[r2][k] : 0.f;
      float n2 = x1*x1 + x2*x2;
      #pragma unroll
      for(int o = 16; o > 0; o >>= 1) n2 += __shfl_xor_sync(0xffffffffu, n2, o);
      float x00 = __shfl_sync(0xffffffffu, x1, 0);   // s[k+1][k]
      float alpha, beta;
      if(n2 < 1e-28f){ alpha = x00; beta = 0.f; }
      else {
        alpha = (x00 >= 0.f) ? -sqrtf(n2) : sqrtf(n2);
        beta  = 1.f/(n2 - alpha*x00);
      }
      if(tid == 0){ sc[0] = alpha; sc[1] = beta; sc[2] = x00; ee[k] = alpha; }
    }
    __syncthreads();
    float beta = sc[1];
    // 2. zero-padded Householder vector at absolute columns
    if(tid < 64){
      float v = 0.f;
      if(beta != 0.f && tid > k)
        v = (tid == k+1) ? (sc[2] - sc[0]) : s[tid][k];
      vc[tid] = v;
    }
    __syncthreads();
    // 3. p_g = beta * (A v)_g : group g handles row g
    {
      const float4* row4 = reinterpret_cast<const float4*>(&s[g][0]);
      float p = 0.f;
      #pragma unroll
      for(int q = 0; q < 4; q++){
        float4 rv = row4[t*4+q];
        float4 vv = vc4[t*4+q];
        p = fmaf(rv.x,vv.x, fmaf(rv.y,vv.y, fmaf(rv.z,vv.z, fmaf(rv.w,vv.w, p))));
      }
      p += __shfl_xor_sync(0xffffffffu, p, 1);
      p += __shfl_xor_sync(0xffffffffu, p, 2);
      if(t == 0) pv[g] = (g > k) ? beta*p : 0.f;
    }
    __syncthreads();
    // 4. K = 0.5*beta*(p^T v) (warp 0), then w = p - K v
    if(tid < 32){
      float a = pv[tid]*vc[tid] + pv[tid+32]*vc[tid+32];
      #pragma unroll
      for(int o = 16; o > 0; o >>= 1) a += __shfl_xor_sync(0xffffffffu, a, o);
      if(tid == 0) sc[3] = 0.5f*beta*a;
    }
    __syncthreads();
    if(tid < 64) wc[tid] = pv[tid] - sc[3]*vc[tid];
    __syncthreads();
    // 5. rank-2 update A -= v w^T + w v^T (rows > k; cols auto-masked by padding)
    if(g > k){
      float vg = vc[g], wg = wc[g];
      float4* u4 = reinterpret_cast<float4*>(&s[g][0]);
      #pragma unroll
      for(int q = 0; q < 4; q++){
        int idx = t*4 + q;
        float4 vv = vc4[idx], ww = wc4[idx];
        float4 r = u4[idx];
        r.x -= vg*ww.x + wg*vv.x;
        r.y -= vg*ww.y + wg*vv.y;
        r.z -= vg*ww.z + wg*vv.z;
        r.w -= vg*ww.w + wg*vv.w;
        u4[idx] = r;
      }
    }
    __syncthreads();
  }

  if(tid == 0) ee[62] = s[63][62];
  __syncthreads();
  if(tid < 64) dd[tid] = s[tid][tid];
  if(tid < 63){ float e = ee[tid]; e2s[tid] = e*e; }
  if(tid == 63) e2s[63] = 0.f;
  __syncthreads();

  // Gershgorin bounds
  if(tid < 64){
    float el = (tid > 0)  ? sqrtf(e2s[tid-1]) : 0.f;
    float er = (tid < 63) ? sqrtf(e2s[tid])   : 0.f;
    vc[tid] = dd[tid] - el - er;
    wc[tid] = dd[tid] + el + er;
  }
  __syncthreads();
  if(tid < 32){
    float lo = fminf(vc[tid], vc[tid+32]);
    float hi = fmaxf(wc[tid], wc[tid+32]);
    #pragma unroll
    for(int o = 16; o > 0; o >>= 1){
      lo = fminf(lo, __shfl_down_sync(0xffffffffu, lo, o));
      hi = fmaxf(hi, __shfl_down_sync(0xffffffffu, hi, o));
    }
    if(tid == 0){ bnd[0] = lo; bnd[1] = hi; }
  }
  __syncthreads();

  // 4-way multisection per eigenvalue
  int j  = tid >> 2;
  int tt = tid & 3;
  int wl = tid & 31;
  unsigned base = wl & ~3u;
  float lo = bnd[0], hi = bnd[1];

  #pragma unroll 1
  for(int r = 0; r < 10; r++){
    float mid = lo + (hi - lo)*0.2f*(float)(tt+1);
    int cnt = 0;
    float q = dd[0] - mid;
    cnt += (q < 0.f);
    #pragma unroll 1
    for(int i = 1; i < 64; i++){
      float aq = fabsf(q);
      float denom = (aq < 1e-25f) ? ((q < 0.f) ? -1e-25f : 1e-25f) : q;
      q = (dd[i] - mid) - __fdividef(e2s[i-1], denom);
      cnt += (q < 0.f);
    }
    int less = (cnt > j);
    #pragma unroll
    for(int s2 = 0; s2 < 4; s2++){
      float ms = __shfl_sync(0xffffffffu, mid,  base + s2);
      int   ls = __shfl_sync(0xffffffffu, less, base + s2);
      if(ls) hi = fminf(hi, ms); else lo = fmaxf(lo, ms);
    }
  }

  float lam = 0.5f*(lo + hi);
  float val = (tt == 0 && lam > 0.f) ? sqrtf(lam) : 0.f;
  #pragma unroll
  for(int o = 16; o > 0; o >>= 1) val += __shfl_down_sync(0xffffffffu, val, o);
  if(wl == 0) red[tid >> 5] = val;
  __syncthreads();
  if(tid == 0){
    float sum = 0.f;
    #pragma unroll
    for(int w = 0; w < 8; w++) sum += red[w];
    g_trace[b] = sum;
  }
}

__global__ void k_final(float* out){
  if(threadIdx.x == 0)
    out[0] = 0.25f*(g_trace[0] + g_trace[1] + g_trace[2] + g_trace[3]);
}

extern "C" void kernel_launch(void* const* d_in, const int* in_sizes, int n_in,
                              void* d_out, int out_size){
  const float* x  = (const float*)d_in[0];
  const float* J  = (const float*)d_in[1];
  const int*   e0 = (const int*)d_in[2];
  const int*   e1 = (const int*)d_in[3];
  int E = in_sizes[2];
  float* out = (float*)d_out;

  k_rowptr<<<(E + 255)/256, 256>>>(e0, E);
  k_phaseA<<<(BB*NN)/8, 256>>>(x, J, e1);
  k_gram<<<dim3(SPLIT, BB), 256>>>();
  k_reduce1<<<dim3(16, 4, BB), 256>>>();
  k_reduce2<<<dim3(16, BB), 256>>>();
  k_eig<<<BB, 256>>>();
  k_final<<<1, 32>>>(out);
}